// round 10
// baseline (speedup 1.0000x reference)
#include <cuda_runtime.h>
#include <math.h>

// ---------------- problem constants ----------------
#define BB 4
#define LL 2048
#define DD 128
#define MM (BB*LL)          // 8192 rows
#define PER_B (DD*LL)       // 262144 elements per batch per [D][L] buffer
#define TOT (BB*PER_B)      // 1048576

typedef unsigned long long u64;

// ---------------- scratch (static device memory; no allocation) ----------------
__device__ float g_pk[TOT];     // projection outputs [b][l][d] == conv input [b][c][s]
__device__ float g_pq[TOT];
__device__ float g_pv[TOT];
__device__ float g_psum[2][3][TOT]; // split-K partials [z][sel]
__device__ float g_ck[TOT];     // conv+silu outputs [b][c][s]
__device__ float g_cq[TOT];
__device__ float g_cv[TOT];
__device__ float g_kT[TOT];     // normalized, transposed [b][t][c]
__device__ float g_qT[TOT];
__device__ float g_vT[TOT];
__device__ float g_dT[TOT];     // delta output [b][t][c]
__device__ float g_normed[TOT]; // rms-normalized delta
__device__ float g_beta[MM];
__device__ float g_kq[MM];      // k_t . q_t
__device__ float g_c[MM];       // k_{t+1} . k_t   (0 at t=2047)
__device__ float g_e[MM];       // q_{t+1} . k_t   (0 at t=2047)
__device__ float g_ninv[2*512]; // inv l2 norms for k (0..511) and q (512..1023)

__device__ __forceinline__ float wsum(float v) {
    #pragma unroll
    for (int o = 16; o > 0; o >>= 1) v += __shfl_xor_sync(0xffffffffu, v, o);
    return v;
}

// ---------------- tf32 helpers ----------------
__device__ __forceinline__ unsigned f2tf32(float x) {
    unsigned r; asm("cvt.rna.tf32.f32 %0, %1;" : "=r"(r) : "f"(x)); return r;
}
__device__ __forceinline__ void mma_tf32(float c[4], const unsigned a[4],
                                         unsigned b0, unsigned b1) {
    asm("mma.sync.aligned.m16n8k8.row.col.f32.tf32.tf32.f32 "
        "{%0,%1,%2,%3}, {%4,%5,%6,%7}, {%8,%9}, {%0,%1,%2,%3};"
        : "+f"(c[0]), "+f"(c[1]), "+f"(c[2]), "+f"(c[3])
        : "r"(a[0]), "r"(a[1]), "r"(a[2]), "r"(a[3]), "r"(b0), "r"(b1));
}
__device__ __forceinline__ void split_sts4(unsigned* dH, unsigned* dL, float4 v) {
    uint4 h, l;
    h.x = f2tf32(v.x); l.x = f2tf32(v.x - __uint_as_float(h.x));
    h.y = f2tf32(v.y); l.y = f2tf32(v.y - __uint_as_float(h.y));
    h.z = f2tf32(v.z); l.z = f2tf32(v.z - __uint_as_float(h.z));
    h.w = f2tf32(v.w); l.w = f2tf32(v.w - __uint_as_float(h.w));
    *(uint4*)dH = h; *(uint4*)dL = l;
}

// =====================================================================
// 3xTF32 tensor-core GEMM core: block tile 128x128, 128 thr, 4 warps
// (2m x 2n), warp tile 64x64 (m16n8k8 tiles 4x8, 3 mma terms).
// BK=8, rows padded to 12 words, DOUBLE-BUFFERED smem (1 sync/ktile,
// STS of next tile overlaps MMA), hi/lo tf32 split at staging.
// bias == nullptr -> raw store (split-K partial mode).
// =====================================================================
__device__ __forceinline__ void gemm3tf32_core_128x128(
    const float* __restrict__ A, int lda,
    const float* __restrict__ Bw, int ldb,
    const float* __restrict__ bias,
    float* __restrict__ C, int ldc,
    int m0, int nkt)
{
    __shared__ unsigned AsH[2][128*12], AsL[2][128*12];
    __shared__ unsigned BsH[2][128*12], BsL[2][128*12];

    const int tid  = threadIdx.x;
    const int w    = tid >> 5, lane = tid & 31;
    const int wm   = w & 1,  wn = w >> 1;
    const int g    = lane >> 2, tg = lane & 3;

    float acc[4][8][4];
    #pragma unroll
    for (int i = 0; i < 4; i++)
        #pragma unroll
        for (int j = 0; j < 8; j++)
            #pragma unroll
            for (int c = 0; c < 4; c++) acc[i][j][c] = 0.f;

    const float* arow = A + (size_t)(m0 + tid) * lda;
    const float* brow = Bw + (size_t)tid * ldb;

    float4 af0 = *(const float4*)(arow);
    float4 af1 = *(const float4*)(arow + 4);
    float4 bf0 = *(const float4*)(brow);
    float4 bf1 = *(const float4*)(brow + 4);
    split_sts4(&AsH[0][tid*12],     &AsL[0][tid*12],     af0);
    split_sts4(&AsH[0][tid*12 + 4], &AsL[0][tid*12 + 4], af1);
    split_sts4(&BsH[0][tid*12],     &BsL[0][tid*12],     bf0);
    split_sts4(&BsH[0][tid*12 + 4], &BsL[0][tid*12 + 4], bf1);
    __syncthreads();

    for (int kt = 0; kt < nkt; ++kt) {
        const int buf = kt & 1;
        if (kt + 1 < nkt) {
            const float* ap = arow + (kt + 1) * 8;
            const float* bp = brow + (kt + 1) * 8;
            af0 = *(const float4*)(ap);
            af1 = *(const float4*)(ap + 4);
            bf0 = *(const float4*)(bp);
            bf1 = *(const float4*)(bp + 4);
        }

        unsigned ah[4][4], al[4][4];
        #pragma unroll
        for (int i = 0; i < 4; i++) {
            int r0 = (wm*64 + i*16 + g) * 12 + tg;
            int r1 = r0 + 96;
            ah[i][0] = AsH[buf][r0];   ah[i][1] = AsH[buf][r1];
            ah[i][2] = AsH[buf][r0+4]; ah[i][3] = AsH[buf][r1+4];
            al[i][0] = AsL[buf][r0];   al[i][1] = AsL[buf][r1];
            al[i][2] = AsL[buf][r0+4]; al[i][3] = AsL[buf][r1+4];
        }
        #pragma unroll
        for (int j = 0; j < 8; j++) {
            int nn = (wn*64 + j*8 + g) * 12 + tg;
            unsigned bh0 = BsH[buf][nn], bh1 = BsH[buf][nn+4];
            unsigned bl0 = BsL[buf][nn], bl1 = BsL[buf][nn+4];
            #pragma unroll
            for (int i = 0; i < 4; i++) {
                mma_tf32(acc[i][j], al[i], bh0, bh1);
                mma_tf32(acc[i][j], ah[i], bl0, bl1);
                mma_tf32(acc[i][j], ah[i], bh0, bh1);
            }
        }

        if (kt + 1 < nkt) {
            const int nb = buf ^ 1;
            split_sts4(&AsH[nb][tid*12],     &AsL[nb][tid*12],     af0);
            split_sts4(&AsH[nb][tid*12 + 4], &AsL[nb][tid*12 + 4], af1);
            split_sts4(&BsH[nb][tid*12],     &BsL[nb][tid*12],     bf0);
            split_sts4(&BsH[nb][tid*12 + 4], &BsL[nb][tid*12 + 4], bf1);
            __syncthreads();
        }
    }
    #pragma unroll
    for (int i = 0; i < 4; i++) {
        const int r = m0 + wm*64 + i*16 + g;
        #pragma unroll
        for (int j = 0; j < 8; j++) {
            const int col = wn*64 + j*8 + tg*2;
            float b0v = 0.f, b1v = 0.f;
            if (bias) { b0v = bias[col]; b1v = bias[col + 1]; }
            float2 o0 = make_float2(acc[i][j][0] + b0v, acc[i][j][1] + b1v);
            float2 o1 = make_float2(acc[i][j][2] + b0v, acc[i][j][3] + b1v);
            *(float2*)(C + (size_t)r * ldc + col)       = o0;
            *(float2*)(C + (size_t)(r + 8) * ldc + col) = o1;
        }
    }
}

// Kernel 1: k/q/v projection GEMM, split-K=2. grid (3, 64, 2) x 128.
__global__ void __launch_bounds__(128) gemm_proj_tf32(
    const float* __restrict__ X,
    const float* __restrict__ Wk, const float* __restrict__ Wq, const float* __restrict__ Wv)
{
    const int sel = blockIdx.x;
    const int z   = blockIdx.z;
    const float* W = (sel == 0) ? Wk : (sel == 1) ? Wq : Wv;
    float* C       = g_psum[z][sel];
    gemm3tf32_core_128x128(X + z * 1024, 2048, W + z * 1024, 2048,
                           nullptr, C, 128, blockIdx.y * 128, 128);
}

// Kernel 1b: reduce split-K halves + bias. grid (1024, 3) x 256.
__global__ void __launch_bounds__(256) reduce_proj(
    const float* __restrict__ bk, const float* __restrict__ bq, const float* __restrict__ bv)
{
    const int sel = blockIdx.y;
    const float* bias = (sel == 0) ? bk : (sel == 1) ? bq : bv;
    float* out        = (sel == 0) ? g_pk : (sel == 1) ? g_pq : g_pv;
    const int i = blockIdx.x * 256 + threadIdx.x;
    float4 a = ((const float4*)g_psum[0][sel])[i];
    float4 b = ((const float4*)g_psum[1][sel])[i];
    float4 bi = ((const float4*)bias)[i & 31];
    float4 o;
    o.x = a.x + b.x + bi.x;
    o.y = a.y + b.y + bi.y;
    o.z = a.z + b.z + bi.z;
    o.w = a.w + b.w + bi.w;
    ((float4*)out)[i] = o;
}

// Kernel 8: output GEMM. grid (16, 64) x 128.
__global__ void __launch_bounds__(128) gemm_out_tf32(
    const float* __restrict__ Wo, const float* __restrict__ bo, float* __restrict__ OUT)
{
    const int n0 = blockIdx.x * 128;
    gemm3tf32_core_128x128(g_normed, 128, Wo + (size_t)n0 * 128, 128,
                           bo + n0, OUT + n0, 2048, blockIdx.y * 128, 16);
}

// =====================================================================
// Kernel 2: beta = sigmoid(x @ beta_w^T + beta_b). One warp per row.
// =====================================================================
__global__ void __launch_bounds__(128) beta_kernel(
    const float* __restrict__ X, const float* __restrict__ bw, const float* __restrict__ bb,
    int m_off)
{
    const int m = m_off + blockIdx.x * 4 + (threadIdx.x >> 5);
    const int lane = threadIdx.x & 31;
    const float4* xr = (const float4*)(X + (size_t)m * 2048);
    const float4* wr = (const float4*)bw;
    float s = 0.f;
    #pragma unroll 4
    for (int i = 0; i < 16; i++) {
        float4 a = xr[i * 32 + lane];
        float4 w = wr[i * 32 + lane];
        s += a.x * w.x + a.y * w.y + a.z * w.z + a.w * w.w;
    }
    s = wsum(s);
    if (lane == 0) g_beta[m] = 1.f / (1.f + expf(-(s + bb[0])));
}

// =====================================================================
// Kernel 3: 1-D conv (k=3 over s, 128->128 ch) + bias + silu.
// =====================================================================
__global__ void __launch_bounds__(256) conv_silu(
    const float* __restrict__ wk, const float* __restrict__ bk,
    const float* __restrict__ wq, const float* __restrict__ bq,
    const float* __restrict__ wv, const float* __restrict__ bv)
{
    const int arr = blockIdx.z >> 2;
    const int b   = blockIdx.z & 3;
    const float* in  = (arr == 0) ? g_pk : (arr == 1) ? g_pq : g_pv;
    float* out       = (arr == 0) ? g_ck : (arr == 1) ? g_cq : g_cv;
    const float* w   = (arr == 0) ? wk : (arr == 1) ? wq : wv;
    const float* bias= (arr == 0) ? bk : (arr == 1) ? bq : bv;

    const int s0 = blockIdx.x * 128;
    const int o0 = blockIdx.y * 64;
    __shared__ float sin_[16][130];
    __shared__ float swt[64][16][3];
    const int tid = threadIdx.x;
    const int to = tid >> 4, ts = tid & 15;
    const int o_loc = to * 4, s_loc = ts * 8;
    const float* inb = in + (size_t)b * PER_B;

    float acc[4][8];
    #pragma unroll
    for (int oo = 0; oo < 4; oo++)
        #pragma unroll
        for (int ss = 0; ss < 8; ss++) acc[oo][ss] = 0.f;

    for (int ic = 0; ic < 8; ic++) {
        for (int i = tid; i < 2080; i += 256) {
            int j = i / 130, p = i % 130;
            int gs = s0 + p - 1;
            sin_[j][p] = (gs >= 0 && gs < 2048) ? inb[(ic * 16 + j) * 2048 + gs] : 0.f;
        }
        for (int i = tid; i < 3072; i += 256) {
            int o = i / 48, rr = i % 48, j = rr / 3, kh = rr % 3;
            swt[o][j][kh] = w[((size_t)(o0 + o) * 128 + ic * 16 + j) * 9 + kh * 3 + 1];
        }
        __syncthreads();
        #pragma unroll
        for (int j = 0; j < 16; j++) {
            float xin[10];
            #pragma unroll
            for (int p = 0; p < 10; p++) xin[p] = sin_[j][s_loc + p];
            #pragma unroll
            for (int oo = 0; oo < 4; oo++) {
                float w0 = swt[o_loc + oo][j][0];
                float w1 = swt[o_loc + oo][j][1];
                float w2 = swt[o_loc + oo][j][2];
                #pragma unroll
                for (int ss = 0; ss < 8; ss++)
                    acc[oo][ss] = fmaf(w0, xin[ss],
                                   fmaf(w1, xin[ss + 1],
                                    fmaf(w2, xin[ss + 2], acc[oo][ss])));
            }
        }
        __syncthreads();
    }
    float* outb = out + (size_t)b * PER_B;
    #pragma unroll
    for (int oo = 0; oo < 4; oo++) {
        float bvv = bias[o0 + o_loc + oo];
        float* orow = outb + (size_t)(o0 + o_loc + oo) * 2048 + s0 + s_loc;
        #pragma unroll
        for (int ss = 0; ss < 8; ss++) {
            float y = acc[oo][ss] + bvv;
            orow[ss] = y / (1.f + expf(-y));
        }
    }
}

// =====================================================================
// Kernel 4: inverse L2 norms over the s axis (2048) for k and q rows.
// =====================================================================
__global__ void __launch_bounds__(128) l2norms()
{
    const int arr = blockIdx.y;
    const int idx = blockIdx.x;
    const float* in = ((arr == 0) ? g_ck : g_cq) + (size_t)idx * 2048;
    const int tid = threadIdx.x;
    float ss = 0.f;
    const float4* in4 = (const float4*)in;
    for (int i = tid; i < 512; i += 128) {
        float4 v = in4[i];
        ss += v.x * v.x + v.y * v.y + v.z * v.z + v.w * v.w;
    }
    ss = wsum(ss);
    __shared__ float red[4];
    if ((tid & 31) == 0) red[tid >> 5] = ss;
    __syncthreads();
    if (tid == 0) {
        float tot = red[0] + red[1] + red[2] + red[3];
        g_ninv[arr * 512 + idx] = 1.f / fmaxf(sqrtf(tot), 1e-12f);
    }
}

// =====================================================================
// Kernel 5: scale (k,q) + transpose all three to [b][t][c].
// =====================================================================
__global__ void transpose_scale()
{
    const int z = blockIdx.z;
    const int arr = z >> 2, b = z & 3;
    const float* in = (arr == 0) ? g_ck : (arr == 1) ? g_cq : g_cv;
    float* out      = (arr == 0) ? g_kT : (arr == 1) ? g_qT : g_vT;
    const int s0 = blockIdx.x * 32, c0 = blockIdx.y * 32;
    __shared__ float tile[32][33];
    const int tx = threadIdx.x, ty = threadIdx.y;
    #pragma unroll
    for (int i = 0; i < 4; i++) {
        int c = c0 + ty + i * 8;
        float sc = (arr < 2) ? g_ninv[arr * 512 + b * 128 + c] : 1.f;
        tile[ty + i * 8][tx] = in[(size_t)b * PER_B + (size_t)c * 2048 + s0 + tx] * sc;
    }
    __syncthreads();
    #pragma unroll
    for (int i = 0; i < 4; i++) {
        int s = s0 + ty + i * 8;
        out[(size_t)b * PER_B + (size_t)s * 128 + c0 + tx] = tile[tx][ty + i * 8];
    }
}

// =====================================================================
// Kernel 5b: per (b,t): kq = k_t.q_t ; c = k_{t+1}.k_t ; e = q_{t+1}.k_t.
// One warp per row m. (c,e zero at t=2047; only even-t values consumed.)
// =====================================================================
__global__ void __launch_bounds__(128) kqce_kernel()
{
    const int m = blockIdx.x * 4 + (threadIdx.x >> 5);
    const int lane = threadIdx.x & 31;
    const int t = m & 2047;
    const float* kr = g_kT + (size_t)m * 128;
    const float* qr = g_qT + (size_t)m * 128;
    float k0 = kr[lane], k1 = kr[lane + 32], k2 = kr[lane + 64], k3 = kr[lane + 96];
    float q0 = qr[lane], q1 = qr[lane + 32], q2 = qr[lane + 64], q3 = qr[lane + 96];
    float skq = fmaf(k3, q3, fmaf(k2, q2, fmaf(k1, q1, k0 * q0)));
    float sc = 0.f, se = 0.f;
    if (t < 2047) {
        const float* kn = kr + 128;
        const float* qn = qr + 128;
        float n0 = kn[lane], n1 = kn[lane + 32], n2 = kn[lane + 64], n3 = kn[lane + 96];
        float m0 = qn[lane], m1 = qn[lane + 32], m2 = qn[lane + 64], m3 = qn[lane + 96];
        sc = fmaf(n3, k3, fmaf(n2, k2, fmaf(n1, k1, n0 * k0)));
        se = fmaf(m3, k3, fmaf(m2, k2, fmaf(m1, k1, m0 * k0)));
    }
    #pragma unroll
    for (int o = 16; o > 0; o >>= 1) {
        skq += __shfl_xor_sync(0xffffffffu, skq, o);
        sc  += __shfl_xor_sync(0xffffffffu, sc, o);
        se  += __shfl_xor_sync(0xffffffffu, se, o);
    }
    if (lane == 0) { g_kq[m] = skq; g_c[m] = sc; g_e[m] = se; }
}

// =====================================================================
// Kernel 6: delta rule, TWO timesteps per round (mini-WY lookahead).
// One warp per (b, row r); lane holds S[r][lane + 32j].
// Per round (t0=2m, t1=2m+1): four reductions (k_t0.s, k_t1.s, q_t0.s,
// q_t1.s) against the SAME s -> one interleaved 5-level shfl pass.
//   u  = b0 (v0 - a1)
//   u2 = b1 (v1 - (a2 + u*c))          c = k_t1.k_t0
//   o0 = d1 + u*kq0
//   o1 = d2 + u*e + u2*kq1             e = q_t1.k_t0
//   s += u k_t0 + u2 k_t1
// Ring prefetch depth 2 rounds (~360 cyc cover > L2 262).
// =====================================================================
__global__ void __launch_bounds__(128) delta_kernel()
{
    const int b  = blockIdx.x >> 5;
    const int rg = blockIdx.x & 31;
    const int warp = threadIdx.x >> 5;
    const int lane = threadIdx.x & 31;
    const int r = rg * 4 + warp;

    const float* kb  = g_kT + (size_t)b * PER_B;
    const float* qb  = g_qT + (size_t)b * PER_B;
    const float* vb  = g_vT + (size_t)b * PER_B;
    const float* bbp = g_beta + b * 2048;
    const float* kqp = g_kq + b * 2048;
    const float* cp  = g_c + b * 2048;
    const float* ep  = g_e + b * 2048;
    float* ob        = g_dT + (size_t)b * PER_B;

    float s0 = 0.f, s1 = 0.f, s2 = 0.f, s3 = 0.f;

    float k0f[2][4], k1f[2][4], q0f[2][4], q1f[2][4];
    float v0f[2], v1f[2], b0f[2], b1f[2], kq0f[2], kq1f[2], cf[2], ef[2];

    #pragma unroll
    for (int j = 0; j < 2; j++) {
        const int t0 = 2 * j, t1 = t0 + 1;
        const float* kp0 = kb + (size_t)t0 * 128;
        const float* kp1 = kb + (size_t)t1 * 128;
        const float* qp0 = qb + (size_t)t0 * 128;
        const float* qp1 = qb + (size_t)t1 * 128;
        k0f[j][0] = kp0[lane]; k0f[j][1] = kp0[lane+32]; k0f[j][2] = kp0[lane+64]; k0f[j][3] = kp0[lane+96];
        k1f[j][0] = kp1[lane]; k1f[j][1] = kp1[lane+32]; k1f[j][2] = kp1[lane+64]; k1f[j][3] = kp1[lane+96];
        q0f[j][0] = qp0[lane]; q0f[j][1] = qp0[lane+32]; q0f[j][2] = qp0[lane+64]; q0f[j][3] = qp0[lane+96];
        q1f[j][0] = qp1[lane]; q1f[j][1] = qp1[lane+32]; q1f[j][2] = qp1[lane+64]; q1f[j][3] = qp1[lane+96];
        v0f[j] = vb[(size_t)t0 * 128 + r]; v1f[j] = vb[(size_t)t1 * 128 + r];
        b0f[j] = bbp[t0]; b1f[j] = bbp[t1];
        kq0f[j] = kqp[t0]; kq1f[j] = kqp[t1];
        cf[j] = cp[t0]; ef[j] = ep[t0];
    }

    for (int m = 0; m < 1024; ++m) {
        const int j = m & 1;
        const int t0 = 2 * m;
        // consume slot j
        float k00 = k0f[j][0], k01 = k0f[j][1], k02 = k0f[j][2], k03 = k0f[j][3];
        float k10 = k1f[j][0], k11 = k1f[j][1], k12 = k1f[j][2], k13 = k1f[j][3];
        float q00 = q0f[j][0], q01 = q0f[j][1], q02 = q0f[j][2], q03 = q0f[j][3];
        float q10 = q1f[j][0], q11 = q1f[j][1], q12 = q1f[j][2], q13 = q1f[j][3];
        float v0 = v0f[j], v1 = v1f[j], be0 = b0f[j], be1 = b1f[j];
        float kq0 = kq0f[j], kq1 = kq1f[j], cc = cf[j], ee = ef[j];

        // refill slot j with round m+2
        if (m + 2 < 1024) {
            const int u0 = 2 * (m + 2), u1 = u0 + 1;
            const float* kp0 = kb + (size_t)u0 * 128;
            const float* kp1 = kb + (size_t)u1 * 128;
            const float* qp0 = qb + (size_t)u0 * 128;
            const float* qp1 = qb + (size_t)u1 * 128;
            k0f[j][0] = kp0[lane]; k0f[j][1] = kp0[lane+32]; k0f[j][2] = kp0[lane+64]; k0f[j][3] = kp0[lane+96];
            k1f[j][0] = kp1[lane]; k1f[j][1] = kp1[lane+32]; k1f[j][2] = kp1[lane+64]; k1f[j][3] = kp1[lane+96];
            q0f[j][0] = qp0[lane]; q0f[j][1] = qp0[lane+32]; q0f[j][2] = qp0[lane+64]; q0f[j][3] = qp0[lane+96];
            q1f[j][0] = qp1[lane]; q1f[j][1] = qp1[lane+32]; q1f[j][2] = qp1[lane+64]; q1f[j][3] = qp1[lane+96];
            v0f[j] = vb[(size_t)u0 * 128 + r]; v1f[j] = vb[(size_t)u1 * 128 + r];
            b0f[j] = bbp[u0]; b1f[j] = bbp[u1];
            kq0f[j] = kqp[u0]; kq1f[j] = kqp[u1];
            cf[j] = cp[u0]; ef[j] = ep[u0];
        }

        // four reductions against the same state
        float a1 = fmaf(k01, s1, k00 * s0) + fmaf(k03, s3, k02 * s2);
        float a2 = fmaf(k11, s1, k10 * s0) + fmaf(k13, s3, k12 * s2);
        float d1 = fmaf(q01, s1, q00 * s0) + fmaf(q03, s3, q02 * s2);
        float d2 = fmaf(q11, s1, q10 * s0) + fmaf(q13, s3, q12 * s2);
        #pragma unroll
        for (int o = 16; o > 0; o >>= 1) {
            a1 += __shfl_xor_sync(0xffffffffu, a1, o);
            a2 += __shfl_xor_sync(0xffffffffu, a2, o);
            d1 += __shfl_xor_sync(0xffffffffu, d1, o);
            d2 += __shfl_xor_sync(0xffffffffu, d2, o);
        }
        float u  = be0 * (v0 - a1);
        float p2 = fmaf(u, cc, a2);
        float u2 = be1 * (v1 - p2);
        if (lane == 0) {
            ob[(size_t)t0 * 128 + r]       = fmaf(u, kq0, d1);
            ob[(size_t)(t0 + 1) * 128 + r] = fmaf(u2, kq1, fmaf(u, ee, d2));
        }
        s0 = fmaf(u2, k10, fmaf(u, k00, s0));
        s1 = fmaf(u2, k11, fmaf(u, k01, s1));
        s2 = fmaf(u2, k12, fmaf(u, k02, s2));
        s3 = fmaf(u2, k13, fmaf(u, k03, s3));
    }
}

// =====================================================================
// Kernel 7: RMS normalize delta over D * rms_w.
// =====================================================================
__global__ void __launch_bounds__(128) rms_kernel(const float* __restrict__ rms_w)
{
    const int m = blockIdx.x * 4 + (threadIdx.x >> 5);
    const int lane = threadIdx.x & 31;
    const float* row = g_dT + (size_t)m * 128;
    float v0 = row[lane], v1 = row[lane + 32], v2 = row[lane + 64], v3 = row[lane + 96];
    float ss = v0 * v0 + v1 * v1 + v2 * v2 + v3 * v3;
    ss = wsum(ss);
    float rs = 1.f / sqrtf(ss * (1.f / 128.f) + 1.1920928955078125e-07f);
    float* o = g_normed + (size_t)m * 128;
    o[lane]      = v0 * rs * rms_w[lane];
    o[lane + 32] = v1 * rs * rms_w[lane + 32];
    o[lane + 64] = v2 * rs * rms_w[lane + 64];
    o[lane + 96] = v3 * rs * rms_w[lane + 96];
}

// =====================================================================
extern "C" void kernel_launch(void* const* d_in, const int* in_sizes, int n_in,
                              void* d_out, int out_size)
{
    const float* x    = (const float*)d_in[0];
    const float* kpw  = (const float*)d_in[1];
    const float* kpb  = (const float*)d_in[2];
    const float* qpw  = (const float*)d_in[3];
    const float* qpb  = (const float*)d_in[4];
    const float* vpw  = (const float*)d_in[5];
    const float* vpb  = (const float*)d_in[6];
    const float* kcw  = (const float*)d_in[7];
    const float* kcb  = (const float*)d_in[8];
    const float* qcw  = (const float*)d_in[9];
    const float* qcb  = (const float*)d_in[10];
    const float* vcw  = (const float*)d_in[11];
    const float* vcb  = (const float*)d_in[12];
    const float* bw   = (const float*)d_in[13];
    const float* bb   = (const float*)d_in[14];
    const float* rmsw = (const float*)d_in[15];
    const float* ow   = (const float*)d_in[16];
    const float* obias= (const float*)d_in[17];
    float* out = (float*)d_out;

    // beta split x3 so the ncu-profiled 4th launch is gemm_proj_tf32
    // (verify the double-buffer effect).
    beta_kernel<<<512, 128>>>(x, bw, bb, 0);
    beta_kernel<<<512, 128>>>(x, bw, bb, 2048);
    beta_kernel<<<1024, 128>>>(x, bw, bb, 4096);
    gemm_proj_tf32<<<dim3(3, 64, 2), 128>>>(x, kpw, qpw, vpw);
    reduce_proj<<<dim3(1024, 3), 256>>>(kpb, qpb, vpb);
    conv_silu<<<dim3(16, 2, 12), 256>>>(kcw, kcb, qcw, qcb, vcw, vcb);
    l2norms<<<dim3(512, 2), 128>>>();
    transpose_scale<<<dim3(64, 4, 12), dim3(32, 8)>>>();
    kqce_kernel<<<2048, 128>>>();
    delta_kernel<<<128, 128>>>();
    rms_kernel<<<2048, 128>>>(rmsw);
    gemm_out_tf32<<<dim3(16, 64), 128>>>(ow, obias, out);
}

// round 11
// speedup vs baseline: 2.2862x; 2.2862x over previous
#include <cuda_runtime.h>
#include <math.h>

// ---------------- problem constants ----------------
#define BB 4
#define LL 2048
#define DD 128
#define MM (BB*LL)          // 8192 rows
#define PER_B (DD*LL)       // 262144 elements per batch per [D][L] buffer
#define TOT (BB*PER_B)      // 1048576

typedef unsigned long long u64;

// ---------------- scratch (static device memory; no allocation) ----------------
__device__ float g_pk[TOT];     // projection outputs [b][l][d] == conv input [b][c][s]
__device__ float g_pq[TOT];
__device__ float g_pv[TOT];
__device__ float g_psum[2][3][TOT]; // split-K partials [z][sel]
__device__ float g_ck[TOT];     // conv+silu outputs [b][c][s]
__device__ float g_cq[TOT];
__device__ float g_cv[TOT];
__device__ float g_kT[TOT];     // normalized, transposed [b][t][c]
__device__ float g_qT[TOT];
__device__ float g_vT[TOT];
__device__ float g_dT[TOT];     // delta output [b][t][c]
__device__ float g_normed[TOT]; // rms-normalized delta
__device__ float g_beta[MM];
__device__ float g_kq[MM];      // k_t . q_t
__device__ float g_c[MM];       // k_{t+1} . k_t   (0 at t=2047)
__device__ float g_e[MM];       // q_{t+1} . k_t   (0 at t=2047)
__device__ float g_ninv[2*512]; // inv l2 norms for k (0..511) and q (512..1023)

__device__ __forceinline__ float wsum(float v) {
    #pragma unroll
    for (int o = 16; o > 0; o >>= 1) v += __shfl_xor_sync(0xffffffffu, v, o);
    return v;
}

// ---------------- tf32 helpers ----------------
__device__ __forceinline__ unsigned f2tf32(float x) {
    unsigned r; asm("cvt.rna.tf32.f32 %0, %1;" : "=r"(r) : "f"(x)); return r;
}
__device__ __forceinline__ void mma_tf32(float c[4], const unsigned a[4],
                                         unsigned b0, unsigned b1) {
    asm("mma.sync.aligned.m16n8k8.row.col.f32.tf32.tf32.f32 "
        "{%0,%1,%2,%3}, {%4,%5,%6,%7}, {%8,%9}, {%0,%1,%2,%3};"
        : "+f"(c[0]), "+f"(c[1]), "+f"(c[2]), "+f"(c[3])
        : "r"(a[0]), "r"(a[1]), "r"(a[2]), "r"(a[3]), "r"(b0), "r"(b1));
}
__device__ __forceinline__ void split_sts4(unsigned* dH, unsigned* dL, float4 v) {
    uint4 h, l;
    h.x = f2tf32(v.x); l.x = f2tf32(v.x - __uint_as_float(h.x));
    h.y = f2tf32(v.y); l.y = f2tf32(v.y - __uint_as_float(h.y));
    h.z = f2tf32(v.z); l.z = f2tf32(v.z - __uint_as_float(h.z));
    h.w = f2tf32(v.w); l.w = f2tf32(v.w - __uint_as_float(h.w));
    *(uint4*)dH = h; *(uint4*)dL = l;
}

// =====================================================================
// 3xTF32 tensor-core GEMM core: block tile 128x128, 128 thr, 4 warps
// (2m x 2n), warp tile 64x64 (m16n8k8 tiles 4x8, 3 mma terms).
// BK=8, rows padded to 12 words, double-buffered smem (1 sync/ktile),
// hi/lo tf32 split at staging. bias == nullptr -> raw store.
// =====================================================================
__device__ __forceinline__ void gemm3tf32_core_128x128(
    const float* __restrict__ A, int lda,
    const float* __restrict__ Bw, int ldb,
    const float* __restrict__ bias,
    float* __restrict__ C, int ldc,
    int m0, int nkt)
{
    __shared__ unsigned AsH[2][128*12], AsL[2][128*12];
    __shared__ unsigned BsH[2][128*12], BsL[2][128*12];

    const int tid  = threadIdx.x;
    const int w    = tid >> 5, lane = tid & 31;
    const int wm   = w & 1,  wn = w >> 1;
    const int g    = lane >> 2, tg = lane & 3;

    float acc[4][8][4];
    #pragma unroll
    for (int i = 0; i < 4; i++)
        #pragma unroll
        for (int j = 0; j < 8; j++)
            #pragma unroll
            for (int c = 0; c < 4; c++) acc[i][j][c] = 0.f;

    const float* arow = A + (size_t)(m0 + tid) * lda;
    const float* brow = Bw + (size_t)tid * ldb;

    float4 af0 = *(const float4*)(arow);
    float4 af1 = *(const float4*)(arow + 4);
    float4 bf0 = *(const float4*)(brow);
    float4 bf1 = *(const float4*)(brow + 4);
    split_sts4(&AsH[0][tid*12],     &AsL[0][tid*12],     af0);
    split_sts4(&AsH[0][tid*12 + 4], &AsL[0][tid*12 + 4], af1);
    split_sts4(&BsH[0][tid*12],     &BsL[0][tid*12],     bf0);
    split_sts4(&BsH[0][tid*12 + 4], &BsL[0][tid*12 + 4], bf1);
    __syncthreads();

    for (int kt = 0; kt < nkt; ++kt) {
        const int buf = kt & 1;
        if (kt + 1 < nkt) {
            const float* ap = arow + (kt + 1) * 8;
            const float* bp = brow + (kt + 1) * 8;
            af0 = *(const float4*)(ap);
            af1 = *(const float4*)(ap + 4);
            bf0 = *(const float4*)(bp);
            bf1 = *(const float4*)(bp + 4);
        }

        unsigned ah[4][4], al[4][4];
        #pragma unroll
        for (int i = 0; i < 4; i++) {
            int r0 = (wm*64 + i*16 + g) * 12 + tg;
            int r1 = r0 + 96;
            ah[i][0] = AsH[buf][r0];   ah[i][1] = AsH[buf][r1];
            ah[i][2] = AsH[buf][r0+4]; ah[i][3] = AsH[buf][r1+4];
            al[i][0] = AsL[buf][r0];   al[i][1] = AsL[buf][r1];
            al[i][2] = AsL[buf][r0+4]; al[i][3] = AsL[buf][r1+4];
        }
        #pragma unroll
        for (int j = 0; j < 8; j++) {
            int nn = (wn*64 + j*8 + g) * 12 + tg;
            unsigned bh0 = BsH[buf][nn], bh1 = BsH[buf][nn+4];
            unsigned bl0 = BsL[buf][nn], bl1 = BsL[buf][nn+4];
            #pragma unroll
            for (int i = 0; i < 4; i++) {
                mma_tf32(acc[i][j], al[i], bh0, bh1);
                mma_tf32(acc[i][j], ah[i], bl0, bl1);
                mma_tf32(acc[i][j], ah[i], bh0, bh1);
            }
        }

        if (kt + 1 < nkt) {
            const int nb = buf ^ 1;
            split_sts4(&AsH[nb][tid*12],     &AsL[nb][tid*12],     af0);
            split_sts4(&AsH[nb][tid*12 + 4], &AsL[nb][tid*12 + 4], af1);
            split_sts4(&BsH[nb][tid*12],     &BsL[nb][tid*12],     bf0);
            split_sts4(&BsH[nb][tid*12 + 4], &BsL[nb][tid*12 + 4], bf1);
            __syncthreads();
        }
    }
    #pragma unroll
    for (int i = 0; i < 4; i++) {
        const int r = m0 + wm*64 + i*16 + g;
        #pragma unroll
        for (int j = 0; j < 8; j++) {
            const int col = wn*64 + j*8 + tg*2;
            float b0v = 0.f, b1v = 0.f;
            if (bias) { b0v = bias[col]; b1v = bias[col + 1]; }
            float2 o0 = make_float2(acc[i][j][0] + b0v, acc[i][j][1] + b1v);
            float2 o1 = make_float2(acc[i][j][2] + b0v, acc[i][j][3] + b1v);
            *(float2*)(C + (size_t)r * ldc + col)       = o0;
            *(float2*)(C + (size_t)(r + 8) * ldc + col) = o1;
        }
    }
}

// Kernel 1: k/q/v projection GEMM, split-K=2. grid (3, 64, 2) x 128.
__global__ void __launch_bounds__(128) gemm_proj_tf32(
    const float* __restrict__ X,
    const float* __restrict__ Wk, const float* __restrict__ Wq, const float* __restrict__ Wv)
{
    const int sel = blockIdx.x;
    const int z   = blockIdx.z;
    const float* W = (sel == 0) ? Wk : (sel == 1) ? Wq : Wv;
    float* C       = g_psum[z][sel];
    gemm3tf32_core_128x128(X + z * 1024, 2048, W + z * 1024, 2048,
                           nullptr, C, 128, blockIdx.y * 128, 128);
}

// Kernel 1b: reduce split-K halves + bias. grid (1024, 3) x 256.
__global__ void __launch_bounds__(256) reduce_proj(
    const float* __restrict__ bk, const float* __restrict__ bq, const float* __restrict__ bv)
{
    const int sel = blockIdx.y;
    const float* bias = (sel == 0) ? bk : (sel == 1) ? bq : bv;
    float* out        = (sel == 0) ? g_pk : (sel == 1) ? g_pq : g_pv;
    const int i = blockIdx.x * 256 + threadIdx.x;
    float4 a = ((const float4*)g_psum[0][sel])[i];
    float4 b = ((const float4*)g_psum[1][sel])[i];
    float4 bi = ((const float4*)bias)[i & 31];
    float4 o;
    o.x = a.x + b.x + bi.x;
    o.y = a.y + b.y + bi.y;
    o.z = a.z + b.z + bi.z;
    o.w = a.w + b.w + bi.w;
    ((float4*)out)[i] = o;
}

// Kernel 8: output GEMM. grid (16, 64) x 128.
__global__ void __launch_bounds__(128) gemm_out_tf32(
    const float* __restrict__ Wo, const float* __restrict__ bo, float* __restrict__ OUT)
{
    const int n0 = blockIdx.x * 128;
    gemm3tf32_core_128x128(g_normed, 128, Wo + (size_t)n0 * 128, 128,
                           bo + n0, OUT + n0, 2048, blockIdx.y * 128, 16);
}

// =====================================================================
// Kernel 2: beta = sigmoid(x @ beta_w^T + beta_b). One warp per row.
// =====================================================================
__global__ void __launch_bounds__(128) beta_kernel(
    const float* __restrict__ X, const float* __restrict__ bw, const float* __restrict__ bb,
    int m_off)
{
    const int m = m_off + blockIdx.x * 4 + (threadIdx.x >> 5);
    const int lane = threadIdx.x & 31;
    const float4* xr = (const float4*)(X + (size_t)m * 2048);
    const float4* wr = (const float4*)bw;
    float s = 0.f;
    #pragma unroll 4
    for (int i = 0; i < 16; i++) {
        float4 a = xr[i * 32 + lane];
        float4 w = wr[i * 32 + lane];
        s += a.x * w.x + a.y * w.y + a.z * w.z + a.w * w.w;
    }
    s = wsum(s);
    if (lane == 0) g_beta[m] = 1.f / (1.f + expf(-(s + bb[0])));
}

// =====================================================================
// Kernel 3: 1-D conv (k=3 over s, 128->128 ch) + bias + silu.
// =====================================================================
__global__ void __launch_bounds__(256) conv_silu(
    const float* __restrict__ wk, const float* __restrict__ bk,
    const float* __restrict__ wq, const float* __restrict__ bq,
    const float* __restrict__ wv, const float* __restrict__ bv)
{
    const int arr = blockIdx.z >> 2;
    const int b   = blockIdx.z & 3;
    const float* in  = (arr == 0) ? g_pk : (arr == 1) ? g_pq : g_pv;
    float* out       = (arr == 0) ? g_ck : (arr == 1) ? g_cq : g_cv;
    const float* w   = (arr == 0) ? wk : (arr == 1) ? wq : wv;
    const float* bias= (arr == 0) ? bk : (arr == 1) ? bq : bv;

    const int s0 = blockIdx.x * 128;
    const int o0 = blockIdx.y * 64;
    __shared__ float sin_[16][130];
    __shared__ float swt[64][16][3];
    const int tid = threadIdx.x;
    const int to = tid >> 4, ts = tid & 15;
    const int o_loc = to * 4, s_loc = ts * 8;
    const float* inb = in + (size_t)b * PER_B;

    float acc[4][8];
    #pragma unroll
    for (int oo = 0; oo < 4; oo++)
        #pragma unroll
        for (int ss = 0; ss < 8; ss++) acc[oo][ss] = 0.f;

    for (int ic = 0; ic < 8; ic++) {
        for (int i = tid; i < 2080; i += 256) {
            int j = i / 130, p = i % 130;
            int gs = s0 + p - 1;
            sin_[j][p] = (gs >= 0 && gs < 2048) ? inb[(ic * 16 + j) * 2048 + gs] : 0.f;
        }
        for (int i = tid; i < 3072; i += 256) {
            int o = i / 48, rr = i % 48, j = rr / 3, kh = rr % 3;
            swt[o][j][kh] = w[((size_t)(o0 + o) * 128 + ic * 16 + j) * 9 + kh * 3 + 1];
        }
        __syncthreads();
        #pragma unroll
        for (int j = 0; j < 16; j++) {
            float xin[10];
            #pragma unroll
            for (int p = 0; p < 10; p++) xin[p] = sin_[j][s_loc + p];
            #pragma unroll
            for (int oo = 0; oo < 4; oo++) {
                float w0 = swt[o_loc + oo][j][0];
                float w1 = swt[o_loc + oo][j][1];
                float w2 = swt[o_loc + oo][j][2];
                #pragma unroll
                for (int ss = 0; ss < 8; ss++)
                    acc[oo][ss] = fmaf(w0, xin[ss],
                                   fmaf(w1, xin[ss + 1],
                                    fmaf(w2, xin[ss + 2], acc[oo][ss])));
            }
        }
        __syncthreads();
    }
    float* outb = out + (size_t)b * PER_B;
    #pragma unroll
    for (int oo = 0; oo < 4; oo++) {
        float bvv = bias[o0 + o_loc + oo];
        float* orow = outb + (size_t)(o0 + o_loc + oo) * 2048 + s0 + s_loc;
        #pragma unroll
        for (int ss = 0; ss < 8; ss++) {
            float y = acc[oo][ss] + bvv;
            orow[ss] = y / (1.f + expf(-y));
        }
    }
}

// =====================================================================
// Kernel 4: inverse L2 norms over the s axis (2048) for k and q rows.
// =====================================================================
__global__ void __launch_bounds__(128) l2norms()
{
    const int arr = blockIdx.y;
    const int idx = blockIdx.x;
    const float* in = ((arr == 0) ? g_ck : g_cq) + (size_t)idx * 2048;
    const int tid = threadIdx.x;
    float ss = 0.f;
    const float4* in4 = (const float4*)in;
    for (int i = tid; i < 512; i += 128) {
        float4 v = in4[i];
        ss += v.x * v.x + v.y * v.y + v.z * v.z + v.w * v.w;
    }
    ss = wsum(ss);
    __shared__ float red[4];
    if ((tid & 31) == 0) red[tid >> 5] = ss;
    __syncthreads();
    if (tid == 0) {
        float tot = red[0] + red[1] + red[2] + red[3];
        g_ninv[arr * 512 + idx] = 1.f / fmaxf(sqrtf(tot), 1e-12f);
    }
}

// =====================================================================
// Kernel 5: scale (k,q) + transpose all three to [b][t][c].
// =====================================================================
__global__ void transpose_scale()
{
    const int z = blockIdx.z;
    const int arr = z >> 2, b = z & 3;
    const float* in = (arr == 0) ? g_ck : (arr == 1) ? g_cq : g_cv;
    float* out      = (arr == 0) ? g_kT : (arr == 1) ? g_qT : g_vT;
    const int s0 = blockIdx.x * 32, c0 = blockIdx.y * 32;
    __shared__ float tile[32][33];
    const int tx = threadIdx.x, ty = threadIdx.y;
    #pragma unroll
    for (int i = 0; i < 4; i++) {
        int c = c0 + ty + i * 8;
        float sc = (arr < 2) ? g_ninv[arr * 512 + b * 128 + c] : 1.f;
        tile[ty + i * 8][tx] = in[(size_t)b * PER_B + (size_t)c * 2048 + s0 + tx] * sc;
    }
    __syncthreads();
    #pragma unroll
    for (int i = 0; i < 4; i++) {
        int s = s0 + ty + i * 8;
        out[(size_t)b * PER_B + (size_t)s * 128 + c0 + tx] = tile[tx][ty + i * 8];
    }
}

// =====================================================================
// Kernel 5b: per (b,t): kq = k_t.q_t ; c = k_{t+1}.k_t ; e = q_{t+1}.k_t.
// One warp per row m. (c,e zero at t=2047; only even-t values consumed.)
// =====================================================================
__global__ void __launch_bounds__(128) kqce_kernel()
{
    const int m = blockIdx.x * 4 + (threadIdx.x >> 5);
    const int lane = threadIdx.x & 31;
    const int t = m & 2047;
    const float* kr = g_kT + (size_t)m * 128;
    const float* qr = g_qT + (size_t)m * 128;
    float k0 = kr[lane], k1 = kr[lane + 32], k2 = kr[lane + 64], k3 = kr[lane + 96];
    float q0 = qr[lane], q1 = qr[lane + 32], q2 = qr[lane + 64], q3 = qr[lane + 96];
    float skq = fmaf(k3, q3, fmaf(k2, q2, fmaf(k1, q1, k0 * q0)));
    float sc = 0.f, se = 0.f;
    if (t < 2047) {
        const float* kn = kr + 128;
        const float* qn = qr + 128;
        float n0 = kn[lane], n1 = kn[lane + 32], n2 = kn[lane + 64], n3 = kn[lane + 96];
        float m0 = qn[lane], m1 = qn[lane + 32], m2 = qn[lane + 64], m3 = qn[lane + 96];
        sc = fmaf(n3, k3, fmaf(n2, k2, fmaf(n1, k1, n0 * k0)));
        se = fmaf(m3, k3, fmaf(m2, k2, fmaf(m1, k1, m0 * k0)));
    }
    #pragma unroll
    for (int o = 16; o > 0; o >>= 1) {
        skq += __shfl_xor_sync(0xffffffffu, skq, o);
        sc  += __shfl_xor_sync(0xffffffffu, sc, o);
        se  += __shfl_xor_sync(0xffffffffu, se, o);
    }
    if (lane == 0) { g_kq[m] = skq; g_c[m] = sc; g_e[m] = se; }
}

// =====================================================================
// Kernel 6: delta rule, TWO timesteps per round (mini-WY lookahead).
// One warp per (b, row r); lane holds S[r][lane + 32j].
// Per round (t0, t0+1): four reductions against the SAME s -> one
// interleaved 5-level shfl pass.
//   u  = b0 (v0 - a1);  u2 = b1 (v1 - (a2 + u*c)),  c = k1.k0
//   o0 = d1 + u*kq0;    o1 = d2 + u*e + u2*kq1,     e = q1.k0
//   s += u k0 + u2 k1
// Ring of 2 rounds with COMPILE-TIME slot indices (mb loop unrolled by
// 2) -- dynamic slot indexing spills the ring to local memory (round-10
// lesson: 4x slowdown).
// =====================================================================
__global__ void __launch_bounds__(128) delta_kernel()
{
    const int b  = blockIdx.x >> 5;
    const int rg = blockIdx.x & 31;
    const int warp = threadIdx.x >> 5;
    const int lane = threadIdx.x & 31;
    const int r = rg * 4 + warp;

    const float* kb  = g_kT + (size_t)b * PER_B;
    const float* qb  = g_qT + (size_t)b * PER_B;
    const float* vb  = g_vT + (size_t)b * PER_B;
    const float* bbp = g_beta + b * 2048;
    const float* kqp = g_kq + b * 2048;
    const float* cp  = g_c + b * 2048;
    const float* ep  = g_e + b * 2048;
    float* ob        = g_dT + (size_t)b * PER_B;

    float s0 = 0.f, s1 = 0.f, s2 = 0.f, s3 = 0.f;

    float k0f[2][4], k1f[2][4], q0f[2][4], q1f[2][4];
    float v0f[2], v1f[2], b0f[2], b1f[2], kq0f[2], kq1f[2], cf[2], ef[2];

    #pragma unroll
    for (int j = 0; j < 2; j++) {
        const int t0 = 2 * j, t1 = t0 + 1;
        const float* kp0 = kb + (size_t)t0 * 128;
        const float* kp1 = kb + (size_t)t1 * 128;
        const float* qp0 = qb + (size_t)t0 * 128;
        const float* qp1 = qb + (size_t)t1 * 128;
        k0f[j][0] = kp0[lane]; k0f[j][1] = kp0[lane+32]; k0f[j][2] = kp0[lane+64]; k0f[j][3] = kp0[lane+96];
        k1f[j][0] = kp1[lane]; k1f[j][1] = kp1[lane+32]; k1f[j][2] = kp1[lane+64]; k1f[j][3] = kp1[lane+96];
        q0f[j][0] = qp0[lane]; q0f[j][1] = qp0[lane+32]; q0f[j][2] = qp0[lane+64]; q0f[j][3] = qp0[lane+96];
        q1f[j][0] = qp1[lane]; q1f[j][1] = qp1[lane+32]; q1f[j][2] = qp1[lane+64]; q1f[j][3] = qp1[lane+96];
        v0f[j] = vb[(size_t)t0 * 128 + r]; v1f[j] = vb[(size_t)t1 * 128 + r];
        b0f[j] = bbp[t0]; b1f[j] = bbp[t1];
        kq0f[j] = kqp[t0]; kq1f[j] = kqp[t1];
        cf[j] = cp[t0]; ef[j] = ep[t0];
    }

    for (int mb = 0; mb < 1024; mb += 2) {
        #pragma unroll
        for (int jj = 0; jj < 2; jj++) {        // jj is COMPILE-TIME
            const int m = mb + jj;
            const int t0 = 2 * m;
            // consume slot jj (static indices -> registers)
            float k00 = k0f[jj][0], k01 = k0f[jj][1], k02 = k0f[jj][2], k03 = k0f[jj][3];
            float k10 = k1f[jj][0], k11 = k1f[jj][1], k12 = k1f[jj][2], k13 = k1f[jj][3];
            float q00 = q0f[jj][0], q01 = q0f[jj][1], q02 = q0f[jj][2], q03 = q0f[jj][3];
            float q10 = q1f[jj][0], q11 = q1f[jj][1], q12 = q1f[jj][2], q13 = q1f[jj][3];
            float v0 = v0f[jj], v1 = v1f[jj], be0 = b0f[jj], be1 = b1f[jj];
            float kq0 = kq0f[jj], kq1 = kq1f[jj], cc = cf[jj], ee = ef[jj];

            // refill slot jj with round m+2 (same parity -> static slot)
            if (m + 2 < 1024) {
                const int u0 = 2 * (m + 2), u1 = u0 + 1;
                const float* kp0 = kb + (size_t)u0 * 128;
                const float* kp1 = kb + (size_t)u1 * 128;
                const float* qp0 = qb + (size_t)u0 * 128;
                const float* qp1 = qb + (size_t)u1 * 128;
                k0f[jj][0] = kp0[lane]; k0f[jj][1] = kp0[lane+32]; k0f[jj][2] = kp0[lane+64]; k0f[jj][3] = kp0[lane+96];
                k1f[jj][0] = kp1[lane]; k1f[jj][1] = kp1[lane+32]; k1f[jj][2] = kp1[lane+64]; k1f[jj][3] = kp1[lane+96];
                q0f[jj][0] = qp0[lane]; q0f[jj][1] = qp0[lane+32]; q0f[jj][2] = qp0[lane+64]; q0f[jj][3] = qp0[lane+96];
                q1f[jj][0] = qp1[lane]; q1f[jj][1] = qp1[lane+32]; q1f[jj][2] = qp1[lane+64]; q1f[jj][3] = qp1[lane+96];
                v0f[jj] = vb[(size_t)u0 * 128 + r]; v1f[jj] = vb[(size_t)u1 * 128 + r];
                b0f[jj] = bbp[u0]; b1f[jj] = bbp[u1];
                kq0f[jj] = kqp[u0]; kq1f[jj] = kqp[u1];
                cf[jj] = cp[u0]; ef[jj] = ep[u0];
            }

            // four reductions against the same state
            float a1 = fmaf(k01, s1, k00 * s0) + fmaf(k03, s3, k02 * s2);
            float a2 = fmaf(k11, s1, k10 * s0) + fmaf(k13, s3, k12 * s2);
            float d1 = fmaf(q01, s1, q00 * s0) + fmaf(q03, s3, q02 * s2);
            float d2 = fmaf(q11, s1, q10 * s0) + fmaf(q13, s3, q12 * s2);
            #pragma unroll
            for (int o = 16; o > 0; o >>= 1) {
                a1 += __shfl_xor_sync(0xffffffffu, a1, o);
                a2 += __shfl_xor_sync(0xffffffffu, a2, o);
                d1 += __shfl_xor_sync(0xffffffffu, d1, o);
                d2 += __shfl_xor_sync(0xffffffffu, d2, o);
            }
            float u  = be0 * (v0 - a1);
            float p2 = fmaf(u, cc, a2);
            float u2 = be1 * (v1 - p2);
            if (lane == 0) {
                ob[(size_t)t0 * 128 + r]       = fmaf(u, kq0, d1);
                ob[(size_t)(t0 + 1) * 128 + r] = fmaf(u2, kq1, fmaf(u, ee, d2));
            }
            s0 = fmaf(u2, k10, fmaf(u, k00, s0));
            s1 = fmaf(u2, k11, fmaf(u, k01, s1));
            s2 = fmaf(u2, k12, fmaf(u, k02, s2));
            s3 = fmaf(u2, k13, fmaf(u, k03, s3));
        }
    }
}

// =====================================================================
// Kernel 7: RMS normalize delta over D * rms_w.
// =====================================================================
__global__ void __launch_bounds__(128) rms_kernel(const float* __restrict__ rms_w)
{
    const int m = blockIdx.x * 4 + (threadIdx.x >> 5);
    const int lane = threadIdx.x & 31;
    const float* row = g_dT + (size_t)m * 128;
    float v0 = row[lane], v1 = row[lane + 32], v2 = row[lane + 64], v3 = row[lane + 96];
    float ss = v0 * v0 + v1 * v1 + v2 * v2 + v3 * v3;
    ss = wsum(ss);
    float rs = 1.f / sqrtf(ss * (1.f / 128.f) + 1.1920928955078125e-07f);
    float* o = g_normed + (size_t)m * 128;
    o[lane]      = v0 * rs * rms_w[lane];
    o[lane + 32] = v1 * rs * rms_w[lane + 32];
    o[lane + 64] = v2 * rs * rms_w[lane + 64];
    o[lane + 96] = v3 * rs * rms_w[lane + 96];
}

// =====================================================================
extern "C" void kernel_launch(void* const* d_in, const int* in_sizes, int n_in,
                              void* d_out, int out_size)
{
    const float* x    = (const float*)d_in[0];
    const float* kpw  = (const float*)d_in[1];
    const float* kpb  = (const float*)d_in[2];
    const float* qpw  = (const float*)d_in[3];
    const float* qpb  = (const float*)d_in[4];
    const float* vpw  = (const float*)d_in[5];
    const float* vpb  = (const float*)d_in[6];
    const float* kcw  = (const float*)d_in[7];
    const float* kcb  = (const float*)d_in[8];
    const float* qcw  = (const float*)d_in[9];
    const float* qcb  = (const float*)d_in[10];
    const float* vcw  = (const float*)d_in[11];
    const float* vcb  = (const float*)d_in[12];
    const float* bw   = (const float*)d_in[13];
    const float* bb   = (const float*)d_in[14];
    const float* rmsw = (const float*)d_in[15];
    const float* ow   = (const float*)d_in[16];
    const float* obias= (const float*)d_in[17];
    float* out = (float*)d_out;

    beta_kernel<<<512, 128>>>(x, bw, bb, 0);
    beta_kernel<<<512, 128>>>(x, bw, bb, 2048);
    beta_kernel<<<1024, 128>>>(x, bw, bb, 4096);
    gemm_proj_tf32<<<dim3(3, 64, 2), 128>>>(x, kpw, qpw, vpw);
    reduce_proj<<<dim3(1024, 3), 256>>>(kpb, qpb, vpb);
    conv_silu<<<dim3(16, 2, 12), 256>>>(kcw, kcb, qcw, qcb, vcw, vcb);
    l2norms<<<dim3(512, 2), 128>>>();
    transpose_scale<<<dim3(64, 4, 12), dim3(32, 8)>>>();
    kqce_kernel<<<2048, 128>>>();
    delta_kernel<<<128, 128>>>();
    rms_kernel<<<2048, 128>>>(rmsw);
    gemm_out_tf32<<<dim3(16, 64), 128>>>(ow, obias, out);
}

// round 12
// speedup vs baseline: 2.6311x; 1.1509x over previous
#include <cuda_runtime.h>
#include <math.h>

// ---------------- problem constants ----------------
#define BB 4
#define LL 2048
#define DD 128
#define MM (BB*LL)          // 8192 rows
#define PER_B (DD*LL)       // 262144 elements per batch per [D][L] buffer
#define TOT (BB*PER_B)      // 1048576

typedef unsigned long long u64;

// ---------------- scratch (static device memory; no allocation) ----------------
__device__ float g_pk[TOT];     // projection outputs [b][l][d] == conv input [b][c][s]
__device__ float g_pq[TOT];
__device__ float g_pv[TOT];
__device__ float g_psum[2][3][TOT]; // split-K partials [z][sel]
__device__ float g_ck[TOT];     // conv+silu outputs [b][c][s]
__device__ float g_cq[TOT];
__device__ float g_cv[TOT];
__device__ float g_kT[TOT];     // normalized, transposed [b][t][c]
__device__ float g_qT[TOT];
__device__ float g_vT[TOT];
__device__ float g_dT[TOT];     // delta output [b][t][c]
__device__ float g_normed[TOT]; // rms-normalized delta
__device__ float g_beta[MM];
__device__ float g_kq[MM];      // k_t . q_t
__device__ float g_c1[MM];      // k_t . k_{t-1}
__device__ float g_c2[MM];      // k_t . k_{t-2}
__device__ float g_c3[MM];      // k_t . k_{t-3}
__device__ float g_e1[MM];      // q_t . k_{t-1}
__device__ float g_e2[MM];      // q_t . k_{t-2}
__device__ float g_e3[MM];      // q_t . k_{t-3}
__device__ float g_ninv[2*512]; // inv l2 norms for k (0..511) and q (512..1023)

__device__ __forceinline__ float wsum(float v) {
    #pragma unroll
    for (int o = 16; o > 0; o >>= 1) v += __shfl_xor_sync(0xffffffffu, v, o);
    return v;
}
__device__ __forceinline__ float dot4f(float4 a, float4 b) {
    float p = fmaf(a.y, b.y, a.x * b.x);
    float q = fmaf(a.w, b.w, a.z * b.z);
    return p + q;
}

// ---------------- tf32 helpers ----------------
__device__ __forceinline__ unsigned f2tf32(float x) {
    unsigned r; asm("cvt.rna.tf32.f32 %0, %1;" : "=r"(r) : "f"(x)); return r;
}
__device__ __forceinline__ void mma_tf32(float c[4], const unsigned a[4],
                                         unsigned b0, unsigned b1) {
    asm("mma.sync.aligned.m16n8k8.row.col.f32.tf32.tf32.f32 "
        "{%0,%1,%2,%3}, {%4,%5,%6,%7}, {%8,%9}, {%0,%1,%2,%3};"
        : "+f"(c[0]), "+f"(c[1]), "+f"(c[2]), "+f"(c[3])
        : "r"(a[0]), "r"(a[1]), "r"(a[2]), "r"(a[3]), "r"(b0), "r"(b1));
}
__device__ __forceinline__ void split_sts4(unsigned* dH, unsigned* dL, float4 v) {
    uint4 h, l;
    h.x = f2tf32(v.x); l.x = f2tf32(v.x - __uint_as_float(h.x));
    h.y = f2tf32(v.y); l.y = f2tf32(v.y - __uint_as_float(h.y));
    h.z = f2tf32(v.z); l.z = f2tf32(v.z - __uint_as_float(h.z));
    h.w = f2tf32(v.w); l.w = f2tf32(v.w - __uint_as_float(h.w));
    *(uint4*)dH = h; *(uint4*)dL = l;
}

// =====================================================================
// 3xTF32 tensor-core GEMM core: block tile 128x128, 128 thr, 4 warps
// (2m x 2n), warp tile 64x64 (m16n8k8 tiles 4x8, 3 mma terms).
// BK=8, rows padded to 12 words, double-buffered smem (1 sync/ktile),
// hi/lo tf32 split at staging. bias == nullptr -> raw store.
// =====================================================================
__device__ __forceinline__ void gemm3tf32_core_128x128(
    const float* __restrict__ A, int lda,
    const float* __restrict__ Bw, int ldb,
    const float* __restrict__ bias,
    float* __restrict__ C, int ldc,
    int m0, int nkt)
{
    __shared__ unsigned AsH[2][128*12], AsL[2][128*12];
    __shared__ unsigned BsH[2][128*12], BsL[2][128*12];

    const int tid  = threadIdx.x;
    const int w    = tid >> 5, lane = tid & 31;
    const int wm   = w & 1,  wn = w >> 1;
    const int g    = lane >> 2, tg = lane & 3;

    float acc[4][8][4];
    #pragma unroll
    for (int i = 0; i < 4; i++)
        #pragma unroll
        for (int j = 0; j < 8; j++)
            #pragma unroll
            for (int c = 0; c < 4; c++) acc[i][j][c] = 0.f;

    const float* arow = A + (size_t)(m0 + tid) * lda;
    const float* brow = Bw + (size_t)tid * ldb;

    float4 af0 = *(const float4*)(arow);
    float4 af1 = *(const float4*)(arow + 4);
    float4 bf0 = *(const float4*)(brow);
    float4 bf1 = *(const float4*)(brow + 4);
    split_sts4(&AsH[0][tid*12],     &AsL[0][tid*12],     af0);
    split_sts4(&AsH[0][tid*12 + 4], &AsL[0][tid*12 + 4], af1);
    split_sts4(&BsH[0][tid*12],     &BsL[0][tid*12],     bf0);
    split_sts4(&BsH[0][tid*12 + 4], &BsL[0][tid*12 + 4], bf1);
    __syncthreads();

    for (int kt = 0; kt < nkt; ++kt) {
        const int buf = kt & 1;
        if (kt + 1 < nkt) {
            const float* ap = arow + (kt + 1) * 8;
            const float* bp = brow + (kt + 1) * 8;
            af0 = *(const float4*)(ap);
            af1 = *(const float4*)(ap + 4);
            bf0 = *(const float4*)(bp);
            bf1 = *(const float4*)(bp + 4);
        }

        unsigned ah[4][4], al[4][4];
        #pragma unroll
        for (int i = 0; i < 4; i++) {
            int r0 = (wm*64 + i*16 + g) * 12 + tg;
            int r1 = r0 + 96;
            ah[i][0] = AsH[buf][r0];   ah[i][1] = AsH[buf][r1];
            ah[i][2] = AsH[buf][r0+4]; ah[i][3] = AsH[buf][r1+4];
            al[i][0] = AsL[buf][r0];   al[i][1] = AsL[buf][r1];
            al[i][2] = AsL[buf][r0+4]; al[i][3] = AsL[buf][r1+4];
        }
        #pragma unroll
        for (int j = 0; j < 8; j++) {
            int nn = (wn*64 + j*8 + g) * 12 + tg;
            unsigned bh0 = BsH[buf][nn], bh1 = BsH[buf][nn+4];
            unsigned bl0 = BsL[buf][nn], bl1 = BsL[buf][nn+4];
            #pragma unroll
            for (int i = 0; i < 4; i++) {
                mma_tf32(acc[i][j], al[i], bh0, bh1);
                mma_tf32(acc[i][j], ah[i], bl0, bl1);
                mma_tf32(acc[i][j], ah[i], bh0, bh1);
            }
        }

        if (kt + 1 < nkt) {
            const int nb = buf ^ 1;
            split_sts4(&AsH[nb][tid*12],     &AsL[nb][tid*12],     af0);
            split_sts4(&AsH[nb][tid*12 + 4], &AsL[nb][tid*12 + 4], af1);
            split_sts4(&BsH[nb][tid*12],     &BsL[nb][tid*12],     bf0);
            split_sts4(&BsH[nb][tid*12 + 4], &BsL[nb][tid*12 + 4], bf1);
            __syncthreads();
        }
    }
    #pragma unroll
    for (int i = 0; i < 4; i++) {
        const int r = m0 + wm*64 + i*16 + g;
        #pragma unroll
        for (int j = 0; j < 8; j++) {
            const int col = wn*64 + j*8 + tg*2;
            float b0v = 0.f, b1v = 0.f;
            if (bias) { b0v = bias[col]; b1v = bias[col + 1]; }
            float2 o0 = make_float2(acc[i][j][0] + b0v, acc[i][j][1] + b1v);
            float2 o1 = make_float2(acc[i][j][2] + b0v, acc[i][j][3] + b1v);
            *(float2*)(C + (size_t)r * ldc + col)       = o0;
            *(float2*)(C + (size_t)(r + 8) * ldc + col) = o1;
        }
    }
}

// Kernel 1: k/q/v projection GEMM, split-K=2. grid (3, 64, 2) x 128.
__global__ void __launch_bounds__(128) gemm_proj_tf32(
    const float* __restrict__ X,
    const float* __restrict__ Wk, const float* __restrict__ Wq, const float* __restrict__ Wv)
{
    const int sel = blockIdx.x;
    const int z   = blockIdx.z;
    const float* W = (sel == 0) ? Wk : (sel == 1) ? Wq : Wv;
    float* C       = g_psum[z][sel];
    gemm3tf32_core_128x128(X + z * 1024, 2048, W + z * 1024, 2048,
                           nullptr, C, 128, blockIdx.y * 128, 128);
}

// Kernel 1b: reduce split-K halves + bias. grid (1024, 3) x 256.
__global__ void __launch_bounds__(256) reduce_proj(
    const float* __restrict__ bk, const float* __restrict__ bq, const float* __restrict__ bv)
{
    const int sel = blockIdx.y;
    const float* bias = (sel == 0) ? bk : (sel == 1) ? bq : bv;
    float* out        = (sel == 0) ? g_pk : (sel == 1) ? g_pq : g_pv;
    const int i = blockIdx.x * 256 + threadIdx.x;
    float4 a = ((const float4*)g_psum[0][sel])[i];
    float4 b = ((const float4*)g_psum[1][sel])[i];
    float4 bi = ((const float4*)bias)[i & 31];
    float4 o;
    o.x = a.x + b.x + bi.x;
    o.y = a.y + b.y + bi.y;
    o.z = a.z + b.z + bi.z;
    o.w = a.w + b.w + bi.w;
    ((float4*)out)[i] = o;
}

// Kernel 8: output GEMM. grid (16, 64) x 128.
__global__ void __launch_bounds__(128) gemm_out_tf32(
    const float* __restrict__ Wo, const float* __restrict__ bo, float* __restrict__ OUT)
{
    const int n0 = blockIdx.x * 128;
    gemm3tf32_core_128x128(g_normed, 128, Wo + (size_t)n0 * 128, 128,
                           bo + n0, OUT + n0, 2048, blockIdx.y * 128, 16);
}

// =====================================================================
// Kernel 2: beta = sigmoid(x @ beta_w^T + beta_b). One warp per row.
// =====================================================================
__global__ void __launch_bounds__(128) beta_kernel(
    const float* __restrict__ X, const float* __restrict__ bw, const float* __restrict__ bb,
    int m_off)
{
    const int m = m_off + blockIdx.x * 4 + (threadIdx.x >> 5);
    const int lane = threadIdx.x & 31;
    const float4* xr = (const float4*)(X + (size_t)m * 2048);
    const float4* wr = (const float4*)bw;
    float s = 0.f;
    #pragma unroll 4
    for (int i = 0; i < 16; i++) {
        float4 a = xr[i * 32 + lane];
        float4 w = wr[i * 32 + lane];
        s += a.x * w.x + a.y * w.y + a.z * w.z + a.w * w.w;
    }
    s = wsum(s);
    if (lane == 0) g_beta[m] = 1.f / (1.f + expf(-(s + bb[0])));
}

// =====================================================================
// Kernel 3: 1-D conv (k=3 over s, 128->128 ch) + bias + silu.
// =====================================================================
__global__ void __launch_bounds__(256) conv_silu(
    const float* __restrict__ wk, const float* __restrict__ bk,
    const float* __restrict__ wq, const float* __restrict__ bq,
    const float* __restrict__ wv, const float* __restrict__ bv)
{
    const int arr = blockIdx.z >> 2;
    const int b   = blockIdx.z & 3;
    const float* in  = (arr == 0) ? g_pk : (arr == 1) ? g_pq : g_pv;
    float* out       = (arr == 0) ? g_ck : (arr == 1) ? g_cq : g_cv;
    const float* w   = (arr == 0) ? wk : (arr == 1) ? wq : wv;
    const float* bias= (arr == 0) ? bk : (arr == 1) ? bq : bv;

    const int s0 = blockIdx.x * 128;
    const int o0 = blockIdx.y * 64;
    __shared__ float sin_[16][130];
    __shared__ float swt[64][16][3];
    const int tid = threadIdx.x;
    const int to = tid >> 4, ts = tid & 15;
    const int o_loc = to * 4, s_loc = ts * 8;
    const float* inb = in + (size_t)b * PER_B;

    float acc[4][8];
    #pragma unroll
    for (int oo = 0; oo < 4; oo++)
        #pragma unroll
        for (int ss = 0; ss < 8; ss++) acc[oo][ss] = 0.f;

    for (int ic = 0; ic < 8; ic++) {
        for (int i = tid; i < 2080; i += 256) {
            int j = i / 130, p = i % 130;
            int gs = s0 + p - 1;
            sin_[j][p] = (gs >= 0 && gs < 2048) ? inb[(ic * 16 + j) * 2048 + gs] : 0.f;
        }
        for (int i = tid; i < 3072; i += 256) {
            int o = i / 48, rr = i % 48, j = rr / 3, kh = rr % 3;
            swt[o][j][kh] = w[((size_t)(o0 + o) * 128 + ic * 16 + j) * 9 + kh * 3 + 1];
        }
        __syncthreads();
        #pragma unroll
        for (int j = 0; j < 16; j++) {
            float xin[10];
            #pragma unroll
            for (int p = 0; p < 10; p++) xin[p] = sin_[j][s_loc + p];
            #pragma unroll
            for (int oo = 0; oo < 4; oo++) {
                float w0 = swt[o_loc + oo][j][0];
                float w1 = swt[o_loc + oo][j][1];
                float w2 = swt[o_loc + oo][j][2];
                #pragma unroll
                for (int ss = 0; ss < 8; ss++)
                    acc[oo][ss] = fmaf(w0, xin[ss],
                                   fmaf(w1, xin[ss + 1],
                                    fmaf(w2, xin[ss + 2], acc[oo][ss])));
            }
        }
        __syncthreads();
    }
    float* outb = out + (size_t)b * PER_B;
    #pragma unroll
    for (int oo = 0; oo < 4; oo++) {
        float bvv = bias[o0 + o_loc + oo];
        float* orow = outb + (size_t)(o0 + o_loc + oo) * 2048 + s0 + s_loc;
        #pragma unroll
        for (int ss = 0; ss < 8; ss++) {
            float y = acc[oo][ss] + bvv;
            orow[ss] = y / (1.f + expf(-y));
        }
    }
}

// =====================================================================
// Kernel 4: inverse L2 norms over the s axis (2048) for k and q rows.
// =====================================================================
__global__ void __launch_bounds__(128) l2norms()
{
    const int arr = blockIdx.y;
    const int idx = blockIdx.x;
    const float* in = ((arr == 0) ? g_ck : g_cq) + (size_t)idx * 2048;
    const int tid = threadIdx.x;
    float ss = 0.f;
    const float4* in4 = (const float4*)in;
    for (int i = tid; i < 512; i += 128) {
        float4 v = in4[i];
        ss += v.x * v.x + v.y * v.y + v.z * v.z + v.w * v.w;
    }
    ss = wsum(ss);
    __shared__ float red[4];
    if ((tid & 31) == 0) red[tid >> 5] = ss;
    __syncthreads();
    if (tid == 0) {
        float tot = red[0] + red[1] + red[2] + red[3];
        g_ninv[arr * 512 + idx] = 1.f / fmaxf(sqrtf(tot), 1e-12f);
    }
}

// =====================================================================
// Kernel 5: scale (k,q) + transpose all three to [b][t][c].
// =====================================================================
__global__ void transpose_scale()
{
    const int z = blockIdx.z;
    const int arr = z >> 2, b = z & 3;
    const float* in = (arr == 0) ? g_ck : (arr == 1) ? g_cq : g_cv;
    float* out      = (arr == 0) ? g_kT : (arr == 1) ? g_qT : g_vT;
    const int s0 = blockIdx.x * 32, c0 = blockIdx.y * 32;
    __shared__ float tile[32][33];
    const int tx = threadIdx.x, ty = threadIdx.y;
    #pragma unroll
    for (int i = 0; i < 4; i++) {
        int c = c0 + ty + i * 8;
        float sc = (arr < 2) ? g_ninv[arr * 512 + b * 128 + c] : 1.f;
        tile[ty + i * 8][tx] = in[(size_t)b * PER_B + (size_t)c * 2048 + s0 + tx] * sc;
    }
    __syncthreads();
    #pragma unroll
    for (int i = 0; i < 4; i++) {
        int s = s0 + ty + i * 8;
        out[(size_t)b * PER_B + (size_t)s * 128 + c0 + tx] = tile[tx][ty + i * 8];
    }
}

// =====================================================================
// Kernel 5b: WY coefficients. One warp per row m = b*2048 + t:
//   kq = k_t.q_t ; c_l = k_t.k_{t-l} ; e_l = q_t.k_{t-l}, l=1..3
// (zero when t < l; those entries are never consumed).
// =====================================================================
__global__ void __launch_bounds__(128) kqce_kernel()
{
    const int m = blockIdx.x * 4 + (threadIdx.x >> 5);
    const int lane = threadIdx.x & 31;
    const int t = m & 2047;
    const float4 k = *(const float4*)(g_kT + (size_t)m * 128 + lane * 4);
    const float4 q = *(const float4*)(g_qT + (size_t)m * 128 + lane * 4);
    float skq = dot4f(k, q);
    float c[3] = {0.f, 0.f, 0.f}, e[3] = {0.f, 0.f, 0.f};
    #pragma unroll
    for (int l = 1; l <= 3; l++) {
        if (t >= l) {
            float4 kl = *(const float4*)(g_kT + (size_t)(m - l) * 128 + lane * 4);
            c[l-1] = dot4f(k, kl);
            e[l-1] = dot4f(q, kl);
        }
    }
    #pragma unroll
    for (int o = 16; o > 0; o >>= 1) {
        skq  += __shfl_xor_sync(0xffffffffu, skq, o);
        c[0] += __shfl_xor_sync(0xffffffffu, c[0], o);
        c[1] += __shfl_xor_sync(0xffffffffu, c[1], o);
        c[2] += __shfl_xor_sync(0xffffffffu, c[2], o);
        e[0] += __shfl_xor_sync(0xffffffffu, e[0], o);
        e[1] += __shfl_xor_sync(0xffffffffu, e[1], o);
        e[2] += __shfl_xor_sync(0xffffffffu, e[2], o);
    }
    if (lane == 0) {
        g_kq[m] = skq;
        g_c1[m] = c[0]; g_c2[m] = c[1]; g_c3[m] = c[2];
        g_e1[m] = e[0]; g_e2[m] = e[1]; g_e3[m] = e[2];
    }
}

// =====================================================================
// Kernel 6: delta rule, FOUR timesteps per round (4-step WY lookahead).
// One warp per (b, row r); lane owns cols [4*lane, 4*lane+3] (float4).
// Per round: 8 reductions (k_i.s, q_i.s, i=0..3) against the SAME s in
// one interleaved 5-level shfl pass. Then serial scalar chain:
//   u0 = b0(v0 - a0)
//   u1 = b1(v1 - a1 - u0*c1[t0+1])
//   u2 = b2(v2 - a2 - u0*c2[t0+2] - u1*c1[t0+2])
//   u3 = b3(v3 - a3 - u0*c3[t0+3] - u1*c2[t0+3] - u2*c1[t0+3])
//   o_i = d_i + sum_{j<i} u_j*e_{i-j}[t0+i] + u_i*kq_i
//   s  += u0 k0 + u1 k1 + u2 k2 + u3 k3
// k/q loads are single LDG.128 per row. Ring depth 2 rounds with
// COMPILE-TIME slot indices (round-10 local-memory lesson).
// =====================================================================
__global__ void __launch_bounds__(128) delta_kernel()
{
    const int b  = blockIdx.x >> 5;
    const int rg = blockIdx.x & 31;
    const int warp = threadIdx.x >> 5;
    const int lane = threadIdx.x & 31;
    const int r = rg * 4 + warp;
    const int c0 = lane * 4;

    const float* kb  = g_kT + (size_t)b * PER_B + c0;
    const float* qb  = g_qT + (size_t)b * PER_B + c0;
    const float* vb  = g_vT + (size_t)b * PER_B + r;
    const float* bbp = g_beta + b * 2048;
    const float* kqp = g_kq + b * 2048;
    const float* c1p = g_c1 + b * 2048;
    const float* c2p = g_c2 + b * 2048;
    const float* c3p = g_c3 + b * 2048;
    const float* e1p = g_e1 + b * 2048;
    const float* e2p = g_e2 + b * 2048;
    const float* e3p = g_e3 + b * 2048;
    float* ob        = g_dT + (size_t)b * PER_B + r;

    float4 s = make_float4(0.f, 0.f, 0.f, 0.f);

    // ring: 2 rounds; per round: 4x k float4, 4x q float4, scalars.
    float4 kf[2][4], qf[2][4];
    float vf[2][4], bf[2][4], kqf[2][4];
    float cA[2], cB[2], cC[2], cD[2], cE[2], cF[2];
    float eA[2], eB[2], eC[2], eD[2], eE[2], eF[2];

    #pragma unroll
    for (int j = 0; j < 2; j++) {
        const int t0 = j * 4;
        #pragma unroll
        for (int i = 0; i < 4; i++) {
            kf[j][i] = *(const float4*)(kb + (size_t)(t0 + i) * 128);
            qf[j][i] = *(const float4*)(qb + (size_t)(t0 + i) * 128);
            vf[j][i] = vb[(size_t)(t0 + i) * 128];
            bf[j][i] = bbp[t0 + i];
            kqf[j][i] = kqp[t0 + i];
        }
        cA[j] = c1p[t0+1]; cB[j] = c1p[t0+2]; cC[j] = c2p[t0+2];
        cD[j] = c1p[t0+3]; cE[j] = c2p[t0+3]; cF[j] = c3p[t0+3];
        eA[j] = e1p[t0+1]; eB[j] = e1p[t0+2]; eC[j] = e2p[t0+2];
        eD[j] = e1p[t0+3]; eE[j] = e2p[t0+3]; eF[j] = e3p[t0+3];
    }

    for (int rb = 0; rb < 512; rb += 2) {
        #pragma unroll
        for (int jj = 0; jj < 2; jj++) {          // COMPILE-TIME slot
            const int m = rb + jj;
            const int t0 = 4 * m;
            float4 k0 = kf[jj][0], k1 = kf[jj][1], k2 = kf[jj][2], k3 = kf[jj][3];
            float4 q0 = qf[jj][0], q1 = qf[jj][1], q2 = qf[jj][2], q3 = qf[jj][3];
            float v0 = vf[jj][0], v1 = vf[jj][1], v2 = vf[jj][2], v3 = vf[jj][3];
            float b0 = bf[jj][0], b1 = bf[jj][1], b2 = bf[jj][2], b3 = bf[jj][3];
            float kq0 = kqf[jj][0], kq1 = kqf[jj][1], kq2 = kqf[jj][2], kq3 = kqf[jj][3];
            float xcA = cA[jj], xcB = cB[jj], xcC = cC[jj], xcD = cD[jj], xcE = cE[jj], xcF = cF[jj];
            float xeA = eA[jj], xeB = eB[jj], xeC = eC[jj], xeD = eD[jj], xeE = eE[jj], xeF = eF[jj];

            // refill slot jj with round m+2 (same parity -> static slot)
            if (m + 2 < 512) {
                const int u0 = 4 * (m + 2);
                #pragma unroll
                for (int i = 0; i < 4; i++) {
                    kf[jj][i] = *(const float4*)(kb + (size_t)(u0 + i) * 128);
                    qf[jj][i] = *(const float4*)(qb + (size_t)(u0 + i) * 128);
                    vf[jj][i] = vb[(size_t)(u0 + i) * 128];
                    bf[jj][i] = bbp[u0 + i];
                    kqf[jj][i] = kqp[u0 + i];
                }
                cA[jj] = c1p[u0+1]; cB[jj] = c1p[u0+2]; cC[jj] = c2p[u0+2];
                cD[jj] = c1p[u0+3]; cE[jj] = c2p[u0+3]; cF[jj] = c3p[u0+3];
                eA[jj] = e1p[u0+1]; eB[jj] = e1p[u0+2]; eC[jj] = e2p[u0+2];
                eD[jj] = e1p[u0+3]; eE[jj] = e2p[u0+3]; eF[jj] = e3p[u0+3];
            }

            // eight reductions against the same state, one interleaved pass
            float a0 = dot4f(k0, s), a1 = dot4f(k1, s);
            float a2 = dot4f(k2, s), a3 = dot4f(k3, s);
            float d0 = dot4f(q0, s), d1 = dot4f(q1, s);
            float d2 = dot4f(q2, s), d3 = dot4f(q3, s);
            #pragma unroll
            for (int o = 16; o > 0; o >>= 1) {
                a0 += __shfl_xor_sync(0xffffffffu, a0, o);
                a1 += __shfl_xor_sync(0xffffffffu, a1, o);
                a2 += __shfl_xor_sync(0xffffffffu, a2, o);
                a3 += __shfl_xor_sync(0xffffffffu, a3, o);
                d0 += __shfl_xor_sync(0xffffffffu, d0, o);
                d1 += __shfl_xor_sync(0xffffffffu, d1, o);
                d2 += __shfl_xor_sync(0xffffffffu, d2, o);
                d3 += __shfl_xor_sync(0xffffffffu, d3, o);
            }
            // serial WY chain
            float u0v = b0 * (v0 - a0);
            float u1v = b1 * (v1 - fmaf(u0v, xcA, a1));
            float u2v = b2 * (v2 - fmaf(u1v, xcB, fmaf(u0v, xcC, a2)));
            float u3v = b3 * (v3 - fmaf(u2v, xcD, fmaf(u1v, xcE, fmaf(u0v, xcF, a3))));
            if (lane == 0) {
                ob[(size_t)t0 * 128]       = fmaf(u0v, kq0, d0);
                ob[(size_t)(t0+1) * 128]   = fmaf(u1v, kq1, fmaf(u0v, xeA, d1));
                ob[(size_t)(t0+2) * 128]   = fmaf(u2v, kq2, fmaf(u1v, xeB, fmaf(u0v, xeC, d2)));
                ob[(size_t)(t0+3) * 128]   = fmaf(u3v, kq3, fmaf(u2v, xeD, fmaf(u1v, xeE, fmaf(u0v, xeF, d3))));
            }
            // state update: s += u0 k0 + u1 k1 + u2 k2 + u3 k3
            s.x = fmaf(u3v, k3.x, fmaf(u2v, k2.x, fmaf(u1v, k1.x, fmaf(u0v, k0.x, s.x))));
            s.y = fmaf(u3v, k3.y, fmaf(u2v, k2.y, fmaf(u1v, k1.y, fmaf(u0v, k0.y, s.y))));
            s.z = fmaf(u3v, k3.z, fmaf(u2v, k2.z, fmaf(u1v, k1.z, fmaf(u0v, k0.z, s.z))));
            s.w = fmaf(u3v, k3.w, fmaf(u2v, k2.w, fmaf(u1v, k1.w, fmaf(u0v, k0.w, s.w))));
        }
    }
}

// =====================================================================
// Kernel 7: RMS normalize delta over D * rms_w.
// =====================================================================
__global__ void __launch_bounds__(128) rms_kernel(const float* __restrict__ rms_w)
{
    const int m = blockIdx.x * 4 + (threadIdx.x >> 5);
    const int lane = threadIdx.x & 31;
    const float* row = g_dT + (size_t)m * 128;
    float v0 = row[lane], v1 = row[lane + 32], v2 = row[lane + 64], v3 = row[lane + 96];
    float ss = v0 * v0 + v1 * v1 + v2 * v2 + v3 * v3;
    ss = wsum(ss);
    float rs = 1.f / sqrtf(ss * (1.f / 128.f) + 1.1920928955078125e-07f);
    float* o = g_normed + (size_t)m * 128;
    o[lane]      = v0 * rs * rms_w[lane];
    o[lane + 32] = v1 * rs * rms_w[lane + 32];
    o[lane + 64] = v2 * rs * rms_w[lane + 64];
    o[lane + 96] = v3 * rs * rms_w[lane + 96];
}

// =====================================================================
extern "C" void kernel_launch(void* const* d_in, const int* in_sizes, int n_in,
                              void* d_out, int out_size)
{
    const float* x    = (const float*)d_in[0];
    const float* kpw  = (const float*)d_in[1];
    const float* kpb  = (const float*)d_in[2];
    const float* qpw  = (const float*)d_in[3];
    const float* qpb  = (const float*)d_in[4];
    const float* vpw  = (const float*)d_in[5];
    const float* vpb  = (const float*)d_in[6];
    const float* kcw  = (const float*)d_in[7];
    const float* kcb  = (const float*)d_in[8];
    const float* qcw  = (const float*)d_in[9];
    const float* qcb  = (const float*)d_in[10];
    const float* vcw  = (const float*)d_in[11];
    const float* vcb  = (const float*)d_in[12];
    const float* bw   = (const float*)d_in[13];
    const float* bb   = (const float*)d_in[14];
    const float* rmsw = (const float*)d_in[15];
    const float* ow   = (const float*)d_in[16];
    const float* obias= (const float*)d_in[17];
    float* out = (float*)d_out;

    beta_kernel<<<512, 128>>>(x, bw, bb, 0);
    beta_kernel<<<512, 128>>>(x, bw, bb, 2048);
    beta_kernel<<<1024, 128>>>(x, bw, bb, 4096);
    gemm_proj_tf32<<<dim3(3, 64, 2), 128>>>(x, kpw, qpw, vpw);
    reduce_proj<<<dim3(1024, 3), 256>>>(kpb, qpb, vpb);
    conv_silu<<<dim3(16, 2, 12), 256>>>(kcw, kcb, qcw, qcb, vcw, vcb);
    l2norms<<<dim3(512, 2), 128>>>();
    transpose_scale<<<dim3(64, 4, 12), dim3(32, 8)>>>();
    kqce_kernel<<<2048, 128>>>();
    delta_kernel<<<128, 128>>>();
    rms_kernel<<<2048, 128>>>(rmsw);
    gemm_out_tf32<<<dim3(16, 64), 128>>>(ow, obias, out);
}

// round 13
// speedup vs baseline: 3.2266x; 1.2263x over previous
#include <cuda_runtime.h>
#include <math.h>

// ---------------- problem constants ----------------
#define BB 4
#define LL 2048
#define DD 128
#define MM (BB*LL)          // 8192 rows
#define PER_B (DD*LL)       // 262144 elements per batch per [D][L] buffer
#define TOT (BB*PER_B)      // 1048576

typedef unsigned long long u64;

// ---------------- scratch (static device memory; no allocation) ----------------
__device__ float g_pk[TOT];     // projection outputs [b][l][d] == conv input [b][c][s]
__device__ float g_pq[TOT];
__device__ float g_pv[TOT];
__device__ float g_psum[2][3][TOT]; // split-K partials [z][sel]
__device__ float g_ck[TOT];     // conv+silu outputs [b][c][s]
__device__ float g_cq[TOT];
__device__ float g_cv[TOT];
__device__ float g_kT[TOT];     // normalized, transposed [b][t][c]
__device__ float g_qT[TOT];
__device__ float g_vT[TOT];
__device__ float g_dT[TOT];     // delta output [b][t][c]
__device__ float g_normed[TOT]; // rms-normalized delta
__device__ float g_beta[MM];
__device__ float g_kq[MM];      // k_t . q_t
__device__ float g_c1[MM];      // k_t . k_{t-1}
__device__ float g_c2[MM];      // k_t . k_{t-2}
__device__ float g_c3[MM];      // k_t . k_{t-3}
__device__ float g_e1[MM];      // q_t . k_{t-1}
__device__ float g_e2[MM];      // q_t . k_{t-2}
__device__ float g_e3[MM];      // q_t . k_{t-3}
__device__ float g_ninv[2*512]; // inv l2 norms for k (0..511) and q (512..1023)

__device__ __forceinline__ float wsum(float v) {
    #pragma unroll
    for (int o = 16; o > 0; o >>= 1) v += __shfl_xor_sync(0xffffffffu, v, o);
    return v;
}
__device__ __forceinline__ float dot4f(float4 a, float4 b) {
    float p = fmaf(a.y, b.y, a.x * b.x);
    float q = fmaf(a.w, b.w, a.z * b.z);
    return p + q;
}

// ---------------- bf16x3 helpers ----------------
// pack2bf(e0, e1): bf16x2 with e0 in the LOW half, e1 in the HIGH half.
__device__ __forceinline__ unsigned pack2bf(float e0, float e1) {
    unsigned r;
    asm("cvt.rn.bf16x2.f32 %0, %1, %2;" : "=r"(r) : "f"(e1), "f"(e0));
    return r;
}
// split 8 fp32 (two float4, consecutive k) into 4 hi-bf16x2 + 4 lo-bf16x2 words.
__device__ __forceinline__ void split_sts8(unsigned* dH, unsigned* dL,
                                           float4 v0, float4 v1) {
    uint4 h, l;
    h.x = pack2bf(v0.x, v0.y);
    l.x = pack2bf(v0.x - __uint_as_float(h.x << 16),
                  v0.y - __uint_as_float(h.x & 0xffff0000u));
    h.y = pack2bf(v0.z, v0.w);
    l.y = pack2bf(v0.z - __uint_as_float(h.y << 16),
                  v0.w - __uint_as_float(h.y & 0xffff0000u));
    h.z = pack2bf(v1.x, v1.y);
    l.z = pack2bf(v1.x - __uint_as_float(h.z << 16),
                  v1.y - __uint_as_float(h.z & 0xffff0000u));
    h.w = pack2bf(v1.z, v1.w);
    l.w = pack2bf(v1.z - __uint_as_float(h.w << 16),
                  v1.w - __uint_as_float(h.w & 0xffff0000u));
    *(uint4*)dH = h; *(uint4*)dL = l;
}
__device__ __forceinline__ void mma_bf16(float c[4], const unsigned a[4],
                                         unsigned b0, unsigned b1) {
    asm("mma.sync.aligned.m16n8k16.row.col.f32.bf16.bf16.f32 "
        "{%0,%1,%2,%3}, {%4,%5,%6,%7}, {%8,%9}, {%0,%1,%2,%3};"
        : "+f"(c[0]), "+f"(c[1]), "+f"(c[2]), "+f"(c[3])
        : "r"(a[0]), "r"(a[1]), "r"(a[2]), "r"(a[3]), "r"(b0), "r"(b1));
}

// =====================================================================
// 3x-BF16 emulated-fp32 tensor-core GEMM core: block tile 128x128,
// 128 thr, 4 warps (2m x 2n), warp tile 64x64 (m16n8k16 tiles 4x8,
// 3 mma terms: AlBh + AhBl + AhBh; AlBl dropped, err ~2^-18).
// BK=16 (k-pairs packed bf16x2, 8 data words + pad -> 12-word rows,
// conflict-free; SAME fragment addressing as the tf32 k8 core).
// Double-buffered smem, 1 sync/ktile. bias == nullptr -> raw store.
// =====================================================================
__device__ __forceinline__ void gemm_bf16x3_core(
    const float* __restrict__ A, int lda,
    const float* __restrict__ Bw, int ldb,
    const float* __restrict__ bias,
    float* __restrict__ C, int ldc,
    int m0, int nkt)
{
    __shared__ unsigned AsH[2][128*12], AsL[2][128*12];
    __shared__ unsigned BsH[2][128*12], BsL[2][128*12];

    const int tid  = threadIdx.x;
    const int w    = tid >> 5, lane = tid & 31;
    const int wm   = w & 1,  wn = w >> 1;
    const int g    = lane >> 2, tg = lane & 3;

    float acc[4][8][4];
    #pragma unroll
    for (int i = 0; i < 4; i++)
        #pragma unroll
        for (int j = 0; j < 8; j++)
            #pragma unroll
            for (int c = 0; c < 4; c++) acc[i][j][c] = 0.f;

    const float* arow = A + (size_t)(m0 + tid) * lda;
    const float* brow = Bw + (size_t)tid * ldb;

    float4 af0 = *(const float4*)(arow);
    float4 af1 = *(const float4*)(arow + 4);
    float4 af2 = *(const float4*)(arow + 8);
    float4 af3 = *(const float4*)(arow + 12);
    float4 bf0 = *(const float4*)(brow);
    float4 bf1 = *(const float4*)(brow + 4);
    float4 bf2 = *(const float4*)(brow + 8);
    float4 bf3 = *(const float4*)(brow + 12);
    split_sts8(&AsH[0][tid*12],     &AsL[0][tid*12],     af0, af1);
    split_sts8(&AsH[0][tid*12 + 4], &AsL[0][tid*12 + 4], af2, af3);
    split_sts8(&BsH[0][tid*12],     &BsL[0][tid*12],     bf0, bf1);
    split_sts8(&BsH[0][tid*12 + 4], &BsL[0][tid*12 + 4], bf2, bf3);
    __syncthreads();

    for (int kt = 0; kt < nkt; ++kt) {
        const int buf = kt & 1;
        if (kt + 1 < nkt) {
            const float* ap = arow + (kt + 1) * 16;
            const float* bp = brow + (kt + 1) * 16;
            af0 = *(const float4*)(ap);      af1 = *(const float4*)(ap + 4);
            af2 = *(const float4*)(ap + 8);  af3 = *(const float4*)(ap + 12);
            bf0 = *(const float4*)(bp);      bf1 = *(const float4*)(bp + 4);
            bf2 = *(const float4*)(bp + 8);  bf3 = *(const float4*)(bp + 12);
        }

        unsigned ah[4][4], al[4][4];
        #pragma unroll
        for (int i = 0; i < 4; i++) {
            int r0 = (wm*64 + i*16 + g) * 12 + tg;
            int r1 = r0 + 96;   // +8 rows
            ah[i][0] = AsH[buf][r0];   ah[i][1] = AsH[buf][r1];
            ah[i][2] = AsH[buf][r0+4]; ah[i][3] = AsH[buf][r1+4];
            al[i][0] = AsL[buf][r0];   al[i][1] = AsL[buf][r1];
            al[i][2] = AsL[buf][r0+4]; al[i][3] = AsL[buf][r1+4];
        }
        #pragma unroll
        for (int j = 0; j < 8; j++) {
            int nn = (wn*64 + j*8 + g) * 12 + tg;
            unsigned bh0 = BsH[buf][nn], bh1 = BsH[buf][nn+4];
            unsigned bl0 = BsL[buf][nn], bl1 = BsL[buf][nn+4];
            #pragma unroll
            for (int i = 0; i < 4; i++) {
                mma_bf16(acc[i][j], al[i], bh0, bh1);   // Alo*Bhi
                mma_bf16(acc[i][j], ah[i], bl0, bl1);   // Ahi*Blo
                mma_bf16(acc[i][j], ah[i], bh0, bh1);   // Ahi*Bhi
            }
        }

        if (kt + 1 < nkt) {
            const int nb = buf ^ 1;
            split_sts8(&AsH[nb][tid*12],     &AsL[nb][tid*12],     af0, af1);
            split_sts8(&AsH[nb][tid*12 + 4], &AsL[nb][tid*12 + 4], af2, af3);
            split_sts8(&BsH[nb][tid*12],     &BsL[nb][tid*12],     bf0, bf1);
            split_sts8(&BsH[nb][tid*12 + 4], &BsL[nb][tid*12 + 4], bf2, bf3);
            __syncthreads();
        }
    }
    #pragma unroll
    for (int i = 0; i < 4; i++) {
        const int r = m0 + wm*64 + i*16 + g;
        #pragma unroll
        for (int j = 0; j < 8; j++) {
            const int col = wn*64 + j*8 + tg*2;
            float b0v = 0.f, b1v = 0.f;
            if (bias) { b0v = bias[col]; b1v = bias[col + 1]; }
            float2 o0 = make_float2(acc[i][j][0] + b0v, acc[i][j][1] + b1v);
            float2 o1 = make_float2(acc[i][j][2] + b0v, acc[i][j][3] + b1v);
            *(float2*)(C + (size_t)r * ldc + col)       = o0;
            *(float2*)(C + (size_t)(r + 8) * ldc + col) = o1;
        }
    }
}

// Kernel 1: k/q/v projection GEMM, split-K=2, BK=16. grid (3, 64, 2) x 128.
__global__ void __launch_bounds__(128) gemm_proj_tf32(
    const float* __restrict__ X,
    const float* __restrict__ Wk, const float* __restrict__ Wq, const float* __restrict__ Wv)
{
    const int sel = blockIdx.x;
    const int z   = blockIdx.z;
    const float* W = (sel == 0) ? Wk : (sel == 1) ? Wq : Wv;
    float* C       = g_psum[z][sel];
    gemm_bf16x3_core(X + z * 1024, 2048, W + z * 1024, 2048,
                     nullptr, C, 128, blockIdx.y * 128, 64);
}

// Kernel 1b: reduce split-K halves + bias. grid (1024, 3) x 256.
__global__ void __launch_bounds__(256) reduce_proj(
    const float* __restrict__ bk, const float* __restrict__ bq, const float* __restrict__ bv)
{
    const int sel = blockIdx.y;
    const float* bias = (sel == 0) ? bk : (sel == 1) ? bq : bv;
    float* out        = (sel == 0) ? g_pk : (sel == 1) ? g_pq : g_pv;
    const int i = blockIdx.x * 256 + threadIdx.x;
    float4 a = ((const float4*)g_psum[0][sel])[i];
    float4 b = ((const float4*)g_psum[1][sel])[i];
    float4 bi = ((const float4*)bias)[i & 31];
    float4 o;
    o.x = a.x + b.x + bi.x;
    o.y = a.y + b.y + bi.y;
    o.z = a.z + b.z + bi.z;
    o.w = a.w + b.w + bi.w;
    ((float4*)out)[i] = o;
}

// Kernel 8: output GEMM, BK=16 (8 ktiles). grid (16, 64) x 128.
__global__ void __launch_bounds__(128) gemm_out_tf32(
    const float* __restrict__ Wo, const float* __restrict__ bo, float* __restrict__ OUT)
{
    const int n0 = blockIdx.x * 128;
    gemm_bf16x3_core(g_normed, 128, Wo + (size_t)n0 * 128, 128,
                     bo + n0, OUT + n0, 2048, blockIdx.y * 128, 8);
}

// =====================================================================
// Kernel 2: beta = sigmoid(x @ beta_w^T + beta_b). One warp per row.
// =====================================================================
__global__ void __launch_bounds__(128) beta_kernel(
    const float* __restrict__ X, const float* __restrict__ bw, const float* __restrict__ bb,
    int m_off)
{
    const int m = m_off + blockIdx.x * 4 + (threadIdx.x >> 5);
    const int lane = threadIdx.x & 31;
    const float4* xr = (const float4*)(X + (size_t)m * 2048);
    const float4* wr = (const float4*)bw;
    float s = 0.f;
    #pragma unroll 4
    for (int i = 0; i < 16; i++) {
        float4 a = xr[i * 32 + lane];
        float4 w = wr[i * 32 + lane];
        s += a.x * w.x + a.y * w.y + a.z * w.z + a.w * w.w;
    }
    s = wsum(s);
    if (lane == 0) g_beta[m] = 1.f / (1.f + expf(-(s + bb[0])));
}

// =====================================================================
// Kernel 3: 1-D conv (k=3 over s, 128->128 ch) + bias + silu.
// =====================================================================
__global__ void __launch_bounds__(256) conv_silu(
    const float* __restrict__ wk, const float* __restrict__ bk,
    const float* __restrict__ wq, const float* __restrict__ bq,
    const float* __restrict__ wv, const float* __restrict__ bv)
{
    const int arr = blockIdx.z >> 2;
    const int b   = blockIdx.z & 3;
    const float* in  = (arr == 0) ? g_pk : (arr == 1) ? g_pq : g_pv;
    float* out       = (arr == 0) ? g_ck : (arr == 1) ? g_cq : g_cv;
    const float* w   = (arr == 0) ? wk : (arr == 1) ? wq : wv;
    const float* bias= (arr == 0) ? bk : (arr == 1) ? bq : bv;

    const int s0 = blockIdx.x * 128;
    const int o0 = blockIdx.y * 64;
    __shared__ float sin_[16][130];
    __shared__ float swt[64][16][3];
    const int tid = threadIdx.x;
    const int to = tid >> 4, ts = tid & 15;
    const int o_loc = to * 4, s_loc = ts * 8;
    const float* inb = in + (size_t)b * PER_B;

    float acc[4][8];
    #pragma unroll
    for (int oo = 0; oo < 4; oo++)
        #pragma unroll
        for (int ss = 0; ss < 8; ss++) acc[oo][ss] = 0.f;

    for (int ic = 0; ic < 8; ic++) {
        for (int i = tid; i < 2080; i += 256) {
            int j = i / 130, p = i % 130;
            int gs = s0 + p - 1;
            sin_[j][p] = (gs >= 0 && gs < 2048) ? inb[(ic * 16 + j) * 2048 + gs] : 0.f;
        }
        for (int i = tid; i < 3072; i += 256) {
            int o = i / 48, rr = i % 48, j = rr / 3, kh = rr % 3;
            swt[o][j][kh] = w[((size_t)(o0 + o) * 128 + ic * 16 + j) * 9 + kh * 3 + 1];
        }
        __syncthreads();
        #pragma unroll
        for (int j = 0; j < 16; j++) {
            float xin[10];
            #pragma unroll
            for (int p = 0; p < 10; p++) xin[p] = sin_[j][s_loc + p];
            #pragma unroll
            for (int oo = 0; oo < 4; oo++) {
                float w0 = swt[o_loc + oo][j][0];
                float w1 = swt[o_loc + oo][j][1];
                float w2 = swt[o_loc + oo][j][2];
                #pragma unroll
                for (int ss = 0; ss < 8; ss++)
                    acc[oo][ss] = fmaf(w0, xin[ss],
                                   fmaf(w1, xin[ss + 1],
                                    fmaf(w2, xin[ss + 2], acc[oo][ss])));
            }
        }
        __syncthreads();
    }
    float* outb = out + (size_t)b * PER_B;
    #pragma unroll
    for (int oo = 0; oo < 4; oo++) {
        float bvv = bias[o0 + o_loc + oo];
        float* orow = outb + (size_t)(o0 + o_loc + oo) * 2048 + s0 + s_loc;
        #pragma unroll
        for (int ss = 0; ss < 8; ss++) {
            float y = acc[oo][ss] + bvv;
            orow[ss] = y / (1.f + expf(-y));
        }
    }
}

// =====================================================================
// Kernel 4: inverse L2 norms over the s axis (2048) for k and q rows.
// =====================================================================
__global__ void __launch_bounds__(128) l2norms()
{
    const int arr = blockIdx.y;
    const int idx = blockIdx.x;
    const float* in = ((arr == 0) ? g_ck : g_cq) + (size_t)idx * 2048;
    const int tid = threadIdx.x;
    float ss = 0.f;
    const float4* in4 = (const float4*)in;
    for (int i = tid; i < 512; i += 128) {
        float4 v = in4[i];
        ss += v.x * v.x + v.y * v.y + v.z * v.z + v.w * v.w;
    }
    ss = wsum(ss);
    __shared__ float red[4];
    if ((tid & 31) == 0) red[tid >> 5] = ss;
    __syncthreads();
    if (tid == 0) {
        float tot = red[0] + red[1] + red[2] + red[3];
        g_ninv[arr * 512 + idx] = 1.f / fmaxf(sqrtf(tot), 1e-12f);
    }
}

// =====================================================================
// Kernel 5: scale (k,q) + transpose all three to [b][t][c].
// =====================================================================
__global__ void transpose_scale()
{
    const int z = blockIdx.z;
    const int arr = z >> 2, b = z & 3;
    const float* in = (arr == 0) ? g_ck : (arr == 1) ? g_cq : g_cv;
    float* out      = (arr == 0) ? g_kT : (arr == 1) ? g_qT : g_vT;
    const int s0 = blockIdx.x * 32, c0 = blockIdx.y * 32;
    __shared__ float tile[32][33];
    const int tx = threadIdx.x, ty = threadIdx.y;
    #pragma unroll
    for (int i = 0; i < 4; i++) {
        int c = c0 + ty + i * 8;
        float sc = (arr < 2) ? g_ninv[arr * 512 + b * 128 + c] : 1.f;
        tile[ty + i * 8][tx] = in[(size_t)b * PER_B + (size_t)c * 2048 + s0 + tx] * sc;
    }
    __syncthreads();
    #pragma unroll
    for (int i = 0; i < 4; i++) {
        int s = s0 + ty + i * 8;
        out[(size_t)b * PER_B + (size_t)s * 128 + c0 + tx] = tile[tx][ty + i * 8];
    }
}

// =====================================================================
// Kernel 5b: WY coefficients. One warp per row m = b*2048 + t:
//   kq = k_t.q_t ; c_l = k_t.k_{t-l} ; e_l = q_t.k_{t-l}, l=1..3
// =====================================================================
__global__ void __launch_bounds__(128) kqce_kernel()
{
    const int m = blockIdx.x * 4 + (threadIdx.x >> 5);
    const int lane = threadIdx.x & 31;
    const int t = m & 2047;
    const float4 k = *(const float4*)(g_kT + (size_t)m * 128 + lane * 4);
    const float4 q = *(const float4*)(g_qT + (size_t)m * 128 + lane * 4);
    float skq = dot4f(k, q);
    float c[3] = {0.f, 0.f, 0.f}, e[3] = {0.f, 0.f, 0.f};
    #pragma unroll
    for (int l = 1; l <= 3; l++) {
        if (t >= l) {
            float4 kl = *(const float4*)(g_kT + (size_t)(m - l) * 128 + lane * 4);
            c[l-1] = dot4f(k, kl);
            e[l-1] = dot4f(q, kl);
        }
    }
    #pragma unroll
    for (int o = 16; o > 0; o >>= 1) {
        skq  += __shfl_xor_sync(0xffffffffu, skq, o);
        c[0] += __shfl_xor_sync(0xffffffffu, c[0], o);
        c[1] += __shfl_xor_sync(0xffffffffu, c[1], o);
        c[2] += __shfl_xor_sync(0xffffffffu, c[2], o);
        e[0] += __shfl_xor_sync(0xffffffffu, e[0], o);
        e[1] += __shfl_xor_sync(0xffffffffu, e[1], o);
        e[2] += __shfl_xor_sync(0xffffffffu, e[2], o);
    }
    if (lane == 0) {
        g_kq[m] = skq;
        g_c1[m] = c[0]; g_c2[m] = c[1]; g_c3[m] = c[2];
        g_e1[m] = e[0]; g_e2[m] = e[1]; g_e3[m] = e[2];
    }
}

// =====================================================================
// Kernel 6: delta rule, FOUR timesteps per round (4-step WY lookahead).
// One warp per (b, row r); lane owns cols [4*lane, 4*lane+3] (float4).
// 8 interleaved reductions/round; serial WY chain; float4 LDG.128 loads;
// ring depth 2 rounds with COMPILE-TIME slot indices.
// =====================================================================
__global__ void __launch_bounds__(128) delta_kernel()
{
    const int b  = blockIdx.x >> 5;
    const int rg = blockIdx.x & 31;
    const int warp = threadIdx.x >> 5;
    const int lane = threadIdx.x & 31;
    const int r = rg * 4 + warp;
    const int c0 = lane * 4;

    const float* kb  = g_kT + (size_t)b * PER_B + c0;
    const float* qb  = g_qT + (size_t)b * PER_B + c0;
    const float* vb  = g_vT + (size_t)b * PER_B + r;
    const float* bbp = g_beta + b * 2048;
    const float* kqp = g_kq + b * 2048;
    const float* c1p = g_c1 + b * 2048;
    const float* c2p = g_c2 + b * 2048;
    const float* c3p = g_c3 + b * 2048;
    const float* e1p = g_e1 + b * 2048;
    const float* e2p = g_e2 + b * 2048;
    const float* e3p = g_e3 + b * 2048;
    float* ob        = g_dT + (size_t)b * PER_B + r;

    float4 s = make_float4(0.f, 0.f, 0.f, 0.f);

    float4 kf[2][4], qf[2][4];
    float vf[2][4], bf[2][4], kqf[2][4];
    float cA[2], cB[2], cC[2], cD[2], cE[2], cF[2];
    float eA[2], eB[2], eC[2], eD[2], eE[2], eF[2];

    #pragma unroll
    for (int j = 0; j < 2; j++) {
        const int t0 = j * 4;
        #pragma unroll
        for (int i = 0; i < 4; i++) {
            kf[j][i] = *(const float4*)(kb + (size_t)(t0 + i) * 128);
            qf[j][i] = *(const float4*)(qb + (size_t)(t0 + i) * 128);
            vf[j][i] = vb[(size_t)(t0 + i) * 128];
            bf[j][i] = bbp[t0 + i];
            kqf[j][i] = kqp[t0 + i];
        }
        cA[j] = c1p[t0+1]; cB[j] = c1p[t0+2]; cC[j] = c2p[t0+2];
        cD[j] = c1p[t0+3]; cE[j] = c2p[t0+3]; cF[j] = c3p[t0+3];
        eA[j] = e1p[t0+1]; eB[j] = e1p[t0+2]; eC[j] = e2p[t0+2];
        eD[j] = e1p[t0+3]; eE[j] = e2p[t0+3]; eF[j] = e3p[t0+3];
    }

    for (int rb = 0; rb < 512; rb += 2) {
        #pragma unroll
        for (int jj = 0; jj < 2; jj++) {          // COMPILE-TIME slot
            const int m = rb + jj;
            const int t0 = 4 * m;
            float4 k0 = kf[jj][0], k1 = kf[jj][1], k2 = kf[jj][2], k3 = kf[jj][3];
            float4 q0 = qf[jj][0], q1 = qf[jj][1], q2 = qf[jj][2], q3 = qf[jj][3];
            float v0 = vf[jj][0], v1 = vf[jj][1], v2 = vf[jj][2], v3 = vf[jj][3];
            float b0 = bf[jj][0], b1 = bf[jj][1], b2 = bf[jj][2], b3 = bf[jj][3];
            float kq0 = kqf[jj][0], kq1 = kqf[jj][1], kq2 = kqf[jj][2], kq3 = kqf[jj][3];
            float xcA = cA[jj], xcB = cB[jj], xcC = cC[jj], xcD = cD[jj], xcE = cE[jj], xcF = cF[jj];
            float xeA = eA[jj], xeB = eB[jj], xeC = eC[jj], xeD = eD[jj], xeE = eE[jj], xeF = eF[jj];

            if (m + 2 < 512) {
                const int u0 = 4 * (m + 2);
                #pragma unroll
                for (int i = 0; i < 4; i++) {
                    kf[jj][i] = *(const float4*)(kb + (size_t)(u0 + i) * 128);
                    qf[jj][i] = *(const float4*)(qb + (size_t)(u0 + i) * 128);
                    vf[jj][i] = vb[(size_t)(u0 + i) * 128];
                    bf[jj][i] = bbp[u0 + i];
                    kqf[jj][i] = kqp[u0 + i];
                }
                cA[jj] = c1p[u0+1]; cB[jj] = c1p[u0+2]; cC[jj] = c2p[u0+2];
                cD[jj] = c1p[u0+3]; cE[jj] = c2p[u0+3]; cF[jj] = c3p[u0+3];
                eA[jj] = e1p[u0+1]; eB[jj] = e1p[u0+2]; eC[jj] = e2p[u0+2];
                eD[jj] = e1p[u0+3]; eE[jj] = e2p[u0+3]; eF[jj] = e3p[u0+3];
            }

            float a0 = dot4f(k0, s), a1 = dot4f(k1, s);
            float a2 = dot4f(k2, s), a3 = dot4f(k3, s);
            float d0 = dot4f(q0, s), d1 = dot4f(q1, s);
            float d2 = dot4f(q2, s), d3 = dot4f(q3, s);
            #pragma unroll
            for (int o = 16; o > 0; o >>= 1) {
                a0 += __shfl_xor_sync(0xffffffffu, a0, o);
                a1 += __shfl_xor_sync(0xffffffffu, a1, o);
                a2 += __shfl_xor_sync(0xffffffffu, a2, o);
                a3 += __shfl_xor_sync(0xffffffffu, a3, o);
                d0 += __shfl_xor_sync(0xffffffffu, d0, o);
                d1 += __shfl_xor_sync(0xffffffffu, d1, o);
                d2 += __shfl_xor_sync(0xffffffffu, d2, o);
                d3 += __shfl_xor_sync(0xffffffffu, d3, o);
            }
            float u0v = b0 * (v0 - a0);
            float u1v = b1 * (v1 - fmaf(u0v, xcA, a1));
            float u2v = b2 * (v2 - fmaf(u1v, xcB, fmaf(u0v, xcC, a2)));
            float u3v = b3 * (v3 - fmaf(u2v, xcD, fmaf(u1v, xcE, fmaf(u0v, xcF, a3))));
            if (lane == 0) {
                ob[(size_t)t0 * 128]       = fmaf(u0v, kq0, d0);
                ob[(size_t)(t0+1) * 128]   = fmaf(u1v, kq1, fmaf(u0v, xeA, d1));
                ob[(size_t)(t0+2) * 128]   = fmaf(u2v, kq2, fmaf(u1v, xeB, fmaf(u0v, xeC, d2)));
                ob[(size_t)(t0+3) * 128]   = fmaf(u3v, kq3, fmaf(u2v, xeD, fmaf(u1v, xeE, fmaf(u0v, xeF, d3))));
            }
            s.x = fmaf(u3v, k3.x, fmaf(u2v, k2.x, fmaf(u1v, k1.x, fmaf(u0v, k0.x, s.x))));
            s.y = fmaf(u3v, k3.y, fmaf(u2v, k2.y, fmaf(u1v, k1.y, fmaf(u0v, k0.y, s.y))));
            s.z = fmaf(u3v, k3.z, fmaf(u2v, k2.z, fmaf(u1v, k1.z, fmaf(u0v, k0.z, s.z))));
            s.w = fmaf(u3v, k3.w, fmaf(u2v, k2.w, fmaf(u1v, k1.w, fmaf(u0v, k0.w, s.w))));
        }
    }
}

// =====================================================================
// Kernel 7: RMS normalize delta over D * rms_w.
// =====================================================================
__global__ void __launch_bounds__(128) rms_kernel(const float* __restrict__ rms_w)
{
    const int m = blockIdx.x * 4 + (threadIdx.x >> 5);
    const int lane = threadIdx.x & 31;
    const float* row = g_dT + (size_t)m * 128;
    float v0 = row[lane], v1 = row[lane + 32], v2 = row[lane + 64], v3 = row[lane + 96];
    float ss = v0 * v0 + v1 * v1 + v2 * v2 + v3 * v3;
    ss = wsum(ss);
    float rs = 1.f / sqrtf(ss * (1.f / 128.f) + 1.1920928955078125e-07f);
    float* o = g_normed + (size_t)m * 128;
    o[lane]      = v0 * rs * rms_w[lane];
    o[lane + 32] = v1 * rs * rms_w[lane + 32];
    o[lane + 64] = v2 * rs * rms_w[lane + 64];
    o[lane + 96] = v3 * rs * rms_w[lane + 96];
}

// =====================================================================
extern "C" void kernel_launch(void* const* d_in, const int* in_sizes, int n_in,
                              void* d_out, int out_size)
{
    const float* x    = (const float*)d_in[0];
    const float* kpw  = (const float*)d_in[1];
    const float* kpb  = (const float*)d_in[2];
    const float* qpw  = (const float*)d_in[3];
    const float* qpb  = (const float*)d_in[4];
    const float* vpw  = (const float*)d_in[5];
    const float* vpb  = (const float*)d_in[6];
    const float* kcw  = (const float*)d_in[7];
    const float* kcb  = (const float*)d_in[8];
    const float* qcw  = (const float*)d_in[9];
    const float* qcb  = (const float*)d_in[10];
    const float* vcw  = (const float*)d_in[11];
    const float* vcb  = (const float*)d_in[12];
    const float* bw   = (const float*)d_in[13];
    const float* bb   = (const float*)d_in[14];
    const float* rmsw = (const float*)d_in[15];
    const float* ow   = (const float*)d_in[16];
    const float* obias= (const float*)d_in[17];
    float* out = (float*)d_out;

    // beta split x3 keeps the ncu-profiled 4th launch on the projection GEMM.
    beta_kernel<<<512, 128>>>(x, bw, bb, 0);
    beta_kernel<<<512, 128>>>(x, bw, bb, 2048);
    beta_kernel<<<1024, 128>>>(x, bw, bb, 4096);
    gemm_proj_tf32<<<dim3(3, 64, 2), 128>>>(x, kpw, qpw, vpw);
    reduce_proj<<<dim3(1024, 3), 256>>>(kpb, qpb, vpb);
    conv_silu<<<dim3(16, 2, 12), 256>>>(kcw, kcb, qcw, qcb, vcw, vcb);
    l2norms<<<dim3(512, 2), 128>>>();
    transpose_scale<<<dim3(64, 4, 12), dim3(32, 8)>>>();
    kqce_kernel<<<2048, 128>>>();
    delta_kernel<<<128, 128>>>();
    rms_kernel<<<2048, 128>>>(rmsw);
    gemm_out_tf32<<<dim3(16, 64), 128>>>(ow, obias, out);
}